// round 1
// baseline (speedup 1.0000x reference)
#include <cuda_runtime.h>
#include <math.h>

#define HID 1024
#define NH  16
#define HD  64
#define NB  4
#define SQL 1024
#define SKV 2048

// Scratch (allocation-free rule: __device__ globals)
__device__ float g_q [(size_t)NB * SQL * HID];        // 16 MB
__device__ float g_kv[(size_t)NB * SKV * 2 * HID];    // 64 MB
__device__ float g_x [(size_t)NB * SQL * HID];        // 16 MB

// ---------------------------------------------------------------------------
// NT SGEMM: C[m,n] = sum_k A[m,k] * B[n,k]  (+ bias[n])
// 64x64 tile, BK=16, 256 threads, 4x4 per thread.
// ---------------------------------------------------------------------------
template<bool BIAS>
__global__ __launch_bounds__(256) void sgemm_nt(
    const float* __restrict__ A, const float* __restrict__ Bm,
    const float* __restrict__ bias, float* __restrict__ C,
    int M, int N, int K)
{
    __shared__ float As[16][68];
    __shared__ float Bs[16][68];

    const int tid = threadIdx.x;
    const int tx  = tid & 15;
    const int ty  = tid >> 4;
    const int m0  = blockIdx.y * 64;
    const int n0  = blockIdx.x * 64;

    const int lrow = tid >> 2;          // 0..63
    const int lk   = (tid & 3) * 4;     // 0,4,8,12

    const float* Ap = A  + (size_t)(m0 + lrow) * K + lk;
    const float* Bp = Bm + (size_t)(n0 + lrow) * K + lk;

    float acc[4][4] = {};

    for (int k0 = 0; k0 < K; k0 += 16) {
        float4 av = *(const float4*)(Ap + k0);
        float4 bv = *(const float4*)(Bp + k0);
        __syncthreads();
        As[lk + 0][lrow] = av.x; As[lk + 1][lrow] = av.y;
        As[lk + 2][lrow] = av.z; As[lk + 3][lrow] = av.w;
        Bs[lk + 0][lrow] = bv.x; Bs[lk + 1][lrow] = bv.y;
        Bs[lk + 2][lrow] = bv.z; Bs[lk + 3][lrow] = bv.w;
        __syncthreads();

        #pragma unroll
        for (int kk = 0; kk < 16; kk++) {
            float4 ra = *(const float4*)&As[kk][ty * 4];
            float4 rb = *(const float4*)&Bs[kk][tx * 4];
            acc[0][0] += ra.x * rb.x; acc[0][1] += ra.x * rb.y;
            acc[0][2] += ra.x * rb.z; acc[0][3] += ra.x * rb.w;
            acc[1][0] += ra.y * rb.x; acc[1][1] += ra.y * rb.y;
            acc[1][2] += ra.y * rb.z; acc[1][3] += ra.y * rb.w;
            acc[2][0] += ra.z * rb.x; acc[2][1] += ra.z * rb.y;
            acc[2][2] += ra.z * rb.z; acc[2][3] += ra.z * rb.w;
            acc[3][0] += ra.w * rb.x; acc[3][1] += ra.w * rb.y;
            acc[3][2] += ra.w * rb.z; acc[3][3] += ra.w * rb.w;
        }
    }

    float4 bb = make_float4(0.f, 0.f, 0.f, 0.f);
    if (BIAS) bb = *(const float4*)(bias + n0 + tx * 4);
    #pragma unroll
    for (int i = 0; i < 4; i++) {
        float4 o = make_float4(acc[i][0] + bb.x, acc[i][1] + bb.y,
                               acc[i][2] + bb.z, acc[i][3] + bb.w);
        *(float4*)(C + (size_t)(m0 + ty * 4 + i) * N + n0 + tx * 4) = o;
    }
}

// ---------------------------------------------------------------------------
// Flash attention: per block = 64 q-rows of one (b,h); KV tiles of 32.
// Online softmax; 256 threads; thread (ty,tx): S 4x2, O 4x4.
// ---------------------------------------------------------------------------
__global__ __launch_bounds__(256) void attn_kernel(
    const float* __restrict__ q, const float* __restrict__ kv,
    float* __restrict__ x)
{
    __shared__ float Qs[64][65];
    __shared__ float Ks[32][65];
    __shared__ float Vs[32][68];
    __shared__ float Ps[64][33];

    const int tid = threadIdx.x;
    const int tx  = tid & 15;
    const int ty  = tid >> 4;
    const int bh  = blockIdx.y;
    const int b   = bh >> 4;
    const int h   = bh & 15;
    const int r0  = blockIdx.x * 64;

    const float* Qp = q  + (size_t)(b * SQL + r0) * HID + h * HD;
    const float* Kp = kv + (size_t)b * SKV * (2 * HID) + h * HD;
    const float* Vp = Kp + HID;

    // Load Q tile 64x64 (4 float4 per thread), scalar smem stores (padded rows)
    #pragma unroll
    for (int t = 0; t < 4; t++) {
        int idx = tid + t * 256;
        int row = idx >> 4;
        int c4  = (idx & 15) * 4;
        float4 v = *(const float4*)(Qp + (size_t)row * HID + c4);
        Qs[row][c4 + 0] = v.x; Qs[row][c4 + 1] = v.y;
        Qs[row][c4 + 2] = v.z; Qs[row][c4 + 3] = v.w;
    }

    float O[4][4] = {};
    float mrow[4] = {-1e30f, -1e30f, -1e30f, -1e30f};
    float lrow[4] = {};
    __syncthreads();

    for (int kv0 = 0; kv0 < SKV; kv0 += 32) {
        // Load K,V tiles 32x64 (2 float4 per thread each)
        #pragma unroll
        for (int t = 0; t < 2; t++) {
            int idx = tid + t * 256;
            int row = idx >> 4;
            int c4  = (idx & 15) * 4;
            float4 kl = *(const float4*)(Kp + (size_t)(kv0 + row) * (2 * HID) + c4);
            Ks[row][c4 + 0] = kl.x; Ks[row][c4 + 1] = kl.y;
            Ks[row][c4 + 2] = kl.z; Ks[row][c4 + 3] = kl.w;
            float4 vl = *(const float4*)(Vp + (size_t)(kv0 + row) * (2 * HID) + c4);
            *(float4*)&Vs[row][c4] = vl;
        }
        __syncthreads();

        // S = Q K^T for this tile: rows ty*4+i, cols tx*2+j
        float s0[4] = {}, s1[4] = {};
        #pragma unroll
        for (int d = 0; d < 64; d++) {
            float b0 = Ks[tx * 2 + 0][d];
            float b1 = Ks[tx * 2 + 1][d];
            #pragma unroll
            for (int i = 0; i < 4; i++) {
                float a = Qs[ty * 4 + i][d];
                s0[i] += a * b0;
                s1[i] += a * b1;
            }
        }

        const float scale = 0.125f;  // 64^-0.5
        #pragma unroll
        for (int i = 0; i < 4; i++) {
            float v0 = s0[i] * scale, v1 = s1[i] * scale;
            float tm = fmaxf(v0, v1);
            #pragma unroll
            for (int off = 8; off; off >>= 1)
                tm = fmaxf(tm, __shfl_xor_sync(0xffffffffu, tm, off));
            float mn   = fmaxf(mrow[i], tm);
            float corr = __expf(mrow[i] - mn);
            float p0   = __expf(v0 - mn);
            float p1   = __expf(v1 - mn);
            float ts   = p0 + p1;
            #pragma unroll
            for (int off = 8; off; off >>= 1)
                ts += __shfl_xor_sync(0xffffffffu, ts, off);
            lrow[i] = lrow[i] * corr + ts;
            mrow[i] = mn;
            O[i][0] *= corr; O[i][1] *= corr; O[i][2] *= corr; O[i][3] *= corr;
            Ps[ty * 4 + i][tx * 2 + 0] = p0;
            Ps[ty * 4 + i][tx * 2 + 1] = p1;
        }
        __syncthreads();

        // O += P @ V  (cols tx*4..tx*4+3 of D)
        #pragma unroll
        for (int k = 0; k < 32; k++) {
            float4 v = *(const float4*)&Vs[k][tx * 4];
            #pragma unroll
            for (int i = 0; i < 4; i++) {
                float p = Ps[ty * 4 + i][k];
                O[i][0] += p * v.x; O[i][1] += p * v.y;
                O[i][2] += p * v.z; O[i][3] += p * v.w;
            }
        }
        __syncthreads();
    }

    #pragma unroll
    for (int i = 0; i < 4; i++) {
        float inv = 1.0f / lrow[i];
        float4 o = make_float4(O[i][0] * inv, O[i][1] * inv,
                               O[i][2] * inv, O[i][3] * inv);
        *(float4*)(x + (size_t)(b * SQL + r0 + ty * 4 + i) * HID + h * HD + tx * 4) = o;
    }
}

// ---------------------------------------------------------------------------
extern "C" void kernel_launch(void* const* d_in, const int* in_sizes, int n_in,
                              void* d_out, int out_size)
{
    const float* xq   = (const float*)d_in[0];
    const float* xkv  = (const float*)d_in[1];
    const float* Wq   = (const float*)d_in[2];
    const float* Wkv  = (const float*)d_in[3];
    const float* Wout = (const float*)d_in[4];
    const float* bout = (const float*)d_in[5];
    float* out = (float*)d_out;

    float *qp, *kvp, *xp;
    cudaGetSymbolAddress((void**)&qp,  g_q);
    cudaGetSymbolAddress((void**)&kvp, g_kv);
    cudaGetSymbolAddress((void**)&xp,  g_x);

    // q = xq @ Wq^T : [4096,1024] x [1024,1024]^T
    sgemm_nt<false><<<dim3(HID / 64, (NB * SQL) / 64), 256>>>(
        xq, Wq, nullptr, qp, NB * SQL, HID, HID);

    // kv = xkv @ Wkv^T : [8192,1024] x [2048,1024]^T
    sgemm_nt<false><<<dim3((2 * HID) / 64, (NB * SKV) / 64), 256>>>(
        xkv, Wkv, nullptr, kvp, NB * SKV, 2 * HID, HID);

    // attention: grid (q-tiles, b*h)
    attn_kernel<<<dim3(SQL / 64, NB * NH), 256>>>(qp, kvp, xp);

    // out = x @ Wout^T + bout
    sgemm_nt<true><<<dim3(HID / 64, (NB * SQL) / 64), 256>>>(
        xp, Wout, bout, out, NB * SQL, HID, HID);
}

// round 2
// speedup vs baseline: 1.2072x; 1.2072x over previous
#include <cuda_runtime.h>
#include <math.h>

#define HID 1024
#define NH  16
#define HD  64
#define NB  4
#define SQL 1024
#define SKV 2048

__device__ float g_q [(size_t)NB * SQL * HID];        // 16 MB
__device__ float g_kv[(size_t)NB * SKV * 2 * HID];    // 64 MB
__device__ float g_x [(size_t)NB * SQL * HID];        // 16 MB

// ---------------------------------------------------------------------------
// NT SGEMM: C[m,n] = sum_k A[m,k]*B[n,k] (+bias[n])
// 128x128 tile, BK=16, 256 threads, 8x8 per thread.
// Smem tiles stored k-major (transposed) so the inner loop is 4 LDS.128
// per 64 FFMA.
// ---------------------------------------------------------------------------
template<bool BIAS>
__global__ __launch_bounds__(256, 2) void sgemm128(
    const float* __restrict__ A, const float* __restrict__ Bm,
    const float* __restrict__ bias, float* __restrict__ C,
    int M, int N, int K)
{
    __shared__ float As[16][132];
    __shared__ float Bs[16][132];

    const int tid = threadIdx.x;
    const int tx  = tid & 15;
    const int ty  = tid >> 4;
    const int m0  = blockIdx.y * 128;
    const int n0  = blockIdx.x * 128;

    const int lr = tid >> 2;          // 0..63
    const int lk = (tid & 3) * 4;     // 0,4,8,12

    const float* Ap = A  + (size_t)(m0 + lr) * K + lk;
    const float* Bp = Bm + (size_t)(n0 + lr) * K + lk;

    float acc[8][8] = {};

    for (int k0 = 0; k0 < K; k0 += 16) {
        float4 a0 = *(const float4*)(Ap + k0);
        float4 a1 = *(const float4*)(Ap + (size_t)64 * K + k0);
        float4 b0 = *(const float4*)(Bp + k0);
        float4 b1 = *(const float4*)(Bp + (size_t)64 * K + k0);
        __syncthreads();
        As[lk+0][lr]    = a0.x; As[lk+1][lr]    = a0.y;
        As[lk+2][lr]    = a0.z; As[lk+3][lr]    = a0.w;
        As[lk+0][lr+64] = a1.x; As[lk+1][lr+64] = a1.y;
        As[lk+2][lr+64] = a1.z; As[lk+3][lr+64] = a1.w;
        Bs[lk+0][lr]    = b0.x; Bs[lk+1][lr]    = b0.y;
        Bs[lk+2][lr]    = b0.z; Bs[lk+3][lr]    = b0.w;
        Bs[lk+0][lr+64] = b1.x; Bs[lk+1][lr+64] = b1.y;
        Bs[lk+2][lr+64] = b1.z; Bs[lk+3][lr+64] = b1.w;
        __syncthreads();

        #pragma unroll
        for (int kk = 0; kk < 16; kk++) {
            float a[8], b[8];
            *(float4*)&a[0] = *(const float4*)&As[kk][ty * 8];
            *(float4*)&a[4] = *(const float4*)&As[kk][ty * 8 + 4];
            *(float4*)&b[0] = *(const float4*)&Bs[kk][tx * 8];
            *(float4*)&b[4] = *(const float4*)&Bs[kk][tx * 8 + 4];
            #pragma unroll
            for (int i = 0; i < 8; i++)
                #pragma unroll
                for (int j = 0; j < 8; j++)
                    acc[i][j] += a[i] * b[j];
        }
    }

    float bv[8] = {};
    if (BIAS) {
        *(float4*)&bv[0] = *(const float4*)(bias + n0 + tx * 8);
        *(float4*)&bv[4] = *(const float4*)(bias + n0 + tx * 8 + 4);
    }
    #pragma unroll
    for (int i = 0; i < 8; i++) {
        float* cp = C + (size_t)(m0 + ty * 8 + i) * N + n0 + tx * 8;
        float4 o0 = make_float4(acc[i][0] + bv[0], acc[i][1] + bv[1],
                                acc[i][2] + bv[2], acc[i][3] + bv[3]);
        float4 o1 = make_float4(acc[i][4] + bv[4], acc[i][5] + bv[5],
                                acc[i][6] + bv[6], acc[i][7] + bv[7]);
        *(float4*)cp       = o0;
        *(float4*)(cp + 4) = o1;
    }
}

// ---------------------------------------------------------------------------
// Flash attention: block = 64 q-rows of one (b,h), KV tiles of 32.
// Q,K stored TRANSPOSED (d-major) in smem so QK^T is a GEMM-style loop:
// per d: 1 LDS.128 (Q, broadcast) + 1 LDS.64 (K) -> 8 FFMA.
// Thread (ty,tx): S is 4 rows x 2 cols, O is 4 rows x 4 d-cols.
// ---------------------------------------------------------------------------
__global__ __launch_bounds__(256) void attn_kernel(
    const float* __restrict__ q, const float* __restrict__ kv,
    float* __restrict__ x)
{
    __shared__ float Qt[64][68];   // [d][qrow], scale pre-applied
    __shared__ float Kt[64][36];   // [d][kvrow]
    __shared__ float Vs[32][68];   // [kvrow][d]
    __shared__ float Ps[64][36];   // [qrow][kvcol]

    const int tid = threadIdx.x;
    const int tx  = tid & 15;
    const int ty  = tid >> 4;
    const int bh  = blockIdx.y;
    const int b   = bh >> 4;
    const int h   = bh & 15;
    const int r0  = blockIdx.x * 64;

    const float* Qp = q  + (size_t)(b * SQL + r0) * HID + h * HD;
    const float* Kp = kv + (size_t)b * SKV * (2 * HID) + h * HD;
    const float* Vp = Kp + HID;

    // Load Q 64x64, store transposed with scale folded in
    {
        const int row = tid >> 2;
        const int d4  = (tid & 3) * 4;
        #pragma unroll
        for (int p = 0; p < 4; p++) {
            int d = d4 + p * 16;
            float4 v = *(const float4*)(Qp + (size_t)row * HID + d);
            Qt[d + 0][row] = v.x * 0.125f;
            Qt[d + 1][row] = v.y * 0.125f;
            Qt[d + 2][row] = v.z * 0.125f;
            Qt[d + 3][row] = v.w * 0.125f;
        }
    }

    float O[4][4] = {};
    float mrow[4] = {-1e30f, -1e30f, -1e30f, -1e30f};
    float lrow[4] = {};

    const int krow = tid >> 3;         // 0..31
    const int kd4  = (tid & 7) * 4;    // 0..28

    for (int kv0 = 0; kv0 < SKV; kv0 += 32) {
        // prefetch K,V tile into regs
        float4 kr[2], vr[2];
        #pragma unroll
        for (int p = 0; p < 2; p++) {
            int d = kd4 + p * 32;
            kr[p] = *(const float4*)(Kp + (size_t)(kv0 + krow) * (2 * HID) + d);
            vr[p] = *(const float4*)(Vp + (size_t)(kv0 + krow) * (2 * HID) + d);
        }
        __syncthreads();   // prev tile's PV done reading Vs/Ps (also covers first-iter Q)
        #pragma unroll
        for (int p = 0; p < 2; p++) {
            int d = kd4 + p * 32;
            Kt[d + 0][krow] = kr[p].x;
            Kt[d + 1][krow] = kr[p].y;
            Kt[d + 2][krow] = kr[p].z;
            Kt[d + 3][krow] = kr[p].w;
            *(float4*)&Vs[krow][d] = vr[p];
        }
        __syncthreads();

        // S = Q K^T : rows ty*4+i, cols tx*2+j
        float s0[4] = {}, s1[4] = {};
        #pragma unroll
        for (int d = 0; d < 64; d++) {
            float4 ra = *(const float4*)&Qt[d][ty * 4];
            float2 rb = *(const float2*)&Kt[d][tx * 2];
            s0[0] += ra.x * rb.x; s1[0] += ra.x * rb.y;
            s0[1] += ra.y * rb.x; s1[1] += ra.y * rb.y;
            s0[2] += ra.z * rb.x; s1[2] += ra.z * rb.y;
            s0[3] += ra.w * rb.x; s1[3] += ra.w * rb.y;
        }

        // online softmax (row reductions across the 16-lane tx group)
        #pragma unroll
        for (int i = 0; i < 4; i++) {
            float tm = fmaxf(s0[i], s1[i]);
            #pragma unroll
            for (int off = 8; off; off >>= 1)
                tm = fmaxf(tm, __shfl_xor_sync(0xffffffffu, tm, off));
            float mn   = fmaxf(mrow[i], tm);
            float corr = __expf(mrow[i] - mn);
            float p0   = __expf(s0[i] - mn);
            float p1   = __expf(s1[i] - mn);
            float ts   = p0 + p1;
            #pragma unroll
            for (int off = 8; off; off >>= 1)
                ts += __shfl_xor_sync(0xffffffffu, ts, off);
            lrow[i] = lrow[i] * corr + ts;
            mrow[i] = mn;
            O[i][0] *= corr; O[i][1] *= corr; O[i][2] *= corr; O[i][3] *= corr;
            *(float2*)&Ps[ty * 4 + i][tx * 2] = make_float2(p0, p1);
        }
        __syncthreads();

        // O += P @ V  (d-cols tx*4..+3)
        #pragma unroll
        for (int k = 0; k < 32; k++) {
            float4 v = *(const float4*)&Vs[k][tx * 4];
            #pragma unroll
            for (int i = 0; i < 4; i++) {
                float p = Ps[ty * 4 + i][k];
                O[i][0] += p * v.x; O[i][1] += p * v.y;
                O[i][2] += p * v.z; O[i][3] += p * v.w;
            }
        }
    }

    #pragma unroll
    for (int i = 0; i < 4; i++) {
        float inv = 1.0f / lrow[i];
        float4 o = make_float4(O[i][0] * inv, O[i][1] * inv,
                               O[i][2] * inv, O[i][3] * inv);
        *(float4*)(x + (size_t)(b * SQL + r0 + ty * 4 + i) * HID + h * HD + tx * 4) = o;
    }
}

// ---------------------------------------------------------------------------
extern "C" void kernel_launch(void* const* d_in, const int* in_sizes, int n_in,
                              void* d_out, int out_size)
{
    const float* xq   = (const float*)d_in[0];
    const float* xkv  = (const float*)d_in[1];
    const float* Wq   = (const float*)d_in[2];
    const float* Wkv  = (const float*)d_in[3];
    const float* Wout = (const float*)d_in[4];
    const float* bout = (const float*)d_in[5];
    float* out = (float*)d_out;

    float *qp, *kvp, *xp;
    cudaGetSymbolAddress((void**)&qp,  g_q);
    cudaGetSymbolAddress((void**)&kvp, g_kv);
    cudaGetSymbolAddress((void**)&xp,  g_x);

    // q = xq @ Wq^T : [4096,1024] x [1024,1024]
    sgemm128<false><<<dim3(HID / 128, (NB * SQL) / 128), 256>>>(
        xq, Wq, nullptr, qp, NB * SQL, HID, HID);

    // kv = xkv @ Wkv^T : [8192,1024] x [2048,1024]
    sgemm128<false><<<dim3((2 * HID) / 128, (NB * SKV) / 128), 256>>>(
        xkv, Wkv, nullptr, kvp, NB * SKV, 2 * HID, HID);

    // attention
    attn_kernel<<<dim3(SQL / 64, NB * NH), 256>>>(qp, kvp, xp);

    // out = x @ Wout^T + bout
    sgemm128<true><<<dim3(HID / 128, (NB * SQL) / 128), 256>>>(
        xp, Wout, bout, out, NB * SQL, HID, HID);
}

// round 4
// speedup vs baseline: 1.6125x; 1.3358x over previous
#include <cuda_runtime.h>
#include <cuda_bf16.h>
#include <math.h>
#include <stdint.h>

#define HID 1024
#define NH  16
#define HD  64
#define NB  4
#define SQL 1024
#define SKV 2048

// ---------------- scratch (__device__ globals; no allocs allowed) ----------
__device__ float g_q [(size_t)NB * SQL * HID];          // 16 MB
__device__ float g_kv[(size_t)NB * SKV * 2 * HID];      // 64 MB
__device__ float g_x [(size_t)NB * SQL * HID];          // 16 MB
// split-bf16: hi in rows [0,R), lo in rows [R,2R)
__device__ __nv_bfloat16 s_xq [(size_t)2 * NB * SQL * HID];
__device__ __nv_bfloat16 s_xkv[(size_t)2 * NB * SKV * HID];
__device__ __nv_bfloat16 s_wq [(size_t)2 * HID * HID];
__device__ __nv_bfloat16 s_wkv[(size_t)2 * 2 * HID * HID];
__device__ __nv_bfloat16 s_wo [(size_t)2 * HID * HID];
__device__ __nv_bfloat16 s_x  [(size_t)2 * NB * SQL * HID];

// ---------------------------------------------------------------------------
static __device__ __forceinline__ uint32_t smem_u32(const void* p) {
    uint32_t a;
    asm("{ .reg .u64 t; cvta.to.shared.u64 t, %1; cvt.u32.u64 %0, t; }"
        : "=r"(a) : "l"(p));
    return a;
}

#define CPA16(dst, src) \
    asm volatile("cp.async.cg.shared.global [%0], [%1], 16;" \
                 :: "r"(dst), "l"(src) : "memory")
#define CPA_COMMIT() asm volatile("cp.async.commit_group;" ::: "memory")
#define CPA_WAIT1()  asm volatile("cp.async.wait_group 1;" ::: "memory")
#define CPA_WAIT0()  asm volatile("cp.async.wait_group 0;" ::: "memory")

#define LDM4(r0, r1, r2, r3, addr) \
    asm volatile("ldmatrix.sync.aligned.m8n8.x4.shared.b16 {%0,%1,%2,%3}, [%4];" \
                 : "=r"(r0), "=r"(r1), "=r"(r2), "=r"(r3) : "r"(addr))

#define MMA16816(d, a, b) \
    asm volatile("mma.sync.aligned.m16n8k16.row.col.f32.bf16.bf16.f32 " \
                 "{%0,%1,%2,%3}, {%4,%5,%6,%7}, {%8,%9}, {%0,%1,%2,%3};" \
                 : "+f"((d)[0]), "+f"((d)[1]), "+f"((d)[2]), "+f"((d)[3]) \
                 : "r"((a)[0]), "r"((a)[1]), "r"((a)[2]), "r"((a)[3]), \
                   "r"((b)[0]), "r"((b)[1]))

// swizzled byte offset of (row, 16B-chunk) in a 128x32-bf16 tile (64B rows)
static __device__ __forceinline__ uint32_t sw(int r, int c) {
    return (uint32_t)(r * 64 + ((c ^ ((r >> 1) & 3)) * 16));
}

// ---------------------------------------------------------------------------
// split fp32 -> (hi, lo) bf16
// ---------------------------------------------------------------------------
__global__ void split_bf16_k(const float* __restrict__ X,
                             __nv_bfloat16* __restrict__ S, int n)
{
    int i = (blockIdx.x * blockDim.x + threadIdx.x) * 4;
    if (i >= n) return;
    float4 x = *(const float4*)(X + i);
    float v[4] = {x.x, x.y, x.z, x.w};
    __nv_bfloat16 h[4], l[4];
    #pragma unroll
    for (int j = 0; j < 4; j++) {
        h[j] = __float2bfloat16(v[j]);
        l[j] = __float2bfloat16(v[j] - __bfloat162float(h[j]));
    }
    *(__nv_bfloat162*)(S + i)         = __halves2bfloat162(h[0], h[1]);
    *(__nv_bfloat162*)(S + i + 2)     = __halves2bfloat162(h[2], h[3]);
    *(__nv_bfloat162*)(S + n + i)     = __halves2bfloat162(l[0], l[1]);
    *(__nv_bfloat162*)(S + n + i + 2) = __halves2bfloat162(l[2], l[3]);
}

// ---------------------------------------------------------------------------
// Split-bf16 NT GEMM via mma.sync: C[m,n] = sum_k A[m,k]*B[n,k] (+bias)
// 128x128 block, BK=32, 8 warps (warp tile 64x32), double-buffered cp.async.
// 96 k-blocks = 3 split segments x (1024/32):
//   seg0: Ah*Bh, seg1: Ah*Bl, seg2: Al*Bh (lo rows start at offset rows*K).
// ---------------------------------------------------------------------------
template<bool BIAS>
__global__ __launch_bounds__(256, 2) void gemm_mma(
    const __nv_bfloat16* __restrict__ A, const __nv_bfloat16* __restrict__ B,
    const float* __restrict__ bias, float* __restrict__ C, int M, int N)
{
    __shared__ __align__(1024) char smem[4 * 8192];  // A0 A1 B0 B1

    const int tid  = threadIdx.x;
    const int wid  = tid >> 5;
    const int lane = tid & 31;
    const int m0   = blockIdx.y * 128;
    const int n0   = blockIdx.x * 128;
    const int wm   = wid & 1;       // 2 warp rows
    const int wn   = wid >> 1;      // 4 warp cols

    const uint32_t sb = smem_u32(smem);
    const size_t MK = (size_t)M * HID, NK = (size_t)N * HID;

    const int NIT = 96;

    #define PREFETCH(it, s) do {                                              \
        int _seg = (it) >> 5, _kb = (it) & 31;                                \
        const __nv_bfloat16* _Ab = A + (_seg == 2 ? MK : 0);                  \
        const __nv_bfloat16* _Bb = B + (_seg == 1 ? NK : 0);                  \
        uint32_t _sa = sb + (s) * 8192;                                       \
        uint32_t _sb2 = sb + 16384 + (s) * 8192;                              \
        _Pragma("unroll")                                                     \
        for (int _q = 0; _q < 2; _q++) {                                      \
            int _ch = tid * 2 + _q;                                           \
            int _r = _ch >> 2, _c = _ch & 3;                                  \
            CPA16(_sa  + sw(_r, _c), _Ab + (size_t)(m0 + _r) * HID + _kb * 32 + _c * 8); \
            CPA16(_sb2 + sw(_r, _c), _Bb + (size_t)(n0 + _r) * HID + _kb * 32 + _c * 8); \
        }                                                                     \
        CPA_COMMIT();                                                         \
    } while (0)

    float d[4][4][4] = {};

    PREFETCH(0, 0);

    for (int it = 0; it < NIT; it++) {
        const int s = it & 1;
        if (it + 1 < NIT) { PREFETCH(it + 1, s ^ 1); CPA_WAIT1(); }
        else              { CPA_WAIT0(); }
        __syncthreads();

        const uint32_t sa  = sb + s * 8192;
        const uint32_t sbm = sb + 16384 + s * 8192;

        #pragma unroll
        for (int ks = 0; ks < 2; ks++) {
            uint32_t a[4][4];
            #pragma unroll
            for (int mi = 0; mi < 4; mi++) {
                int r = wm * 64 + mi * 16 + ((lane >> 3) & 1) * 8 + (lane & 7);
                int c = ks * 2 + ((lane >> 4) & 1);
                LDM4(a[mi][0], a[mi][1], a[mi][2], a[mi][3], sa + sw(r, c));
            }
            uint32_t b[4][2];
            #pragma unroll
            for (int ni = 0; ni < 2; ni++) {
                int r = wn * 32 + ni * 16 + ((lane >> 4) & 1) * 8 + (lane & 7);
                int c = ks * 2 + ((lane >> 3) & 1);
                uint32_t r0, r1, r2, r3;
                LDM4(r0, r1, r2, r3, sbm + sw(r, c));
                b[ni * 2][0] = r0; b[ni * 2][1] = r1;
                b[ni * 2 + 1][0] = r2; b[ni * 2 + 1][1] = r3;
            }
            #pragma unroll
            for (int mi = 0; mi < 4; mi++)
                #pragma unroll
                for (int nj = 0; nj < 4; nj++)
                    MMA16816(d[mi][nj], a[mi], b[nj]);
        }
        __syncthreads();
    }

    // epilogue
    const int row0 = m0 + wm * 64 + (lane >> 2);
    const int col0 = n0 + wn * 32 + (lane & 3) * 2;
    #pragma unroll
    for (int mi = 0; mi < 4; mi++) {
        #pragma unroll
        for (int nj = 0; nj < 4; nj++) {
            int r = row0 + mi * 16;
            int cc = col0 + nj * 8;
            float b0 = 0.f, b1 = 0.f;
            if (BIAS) { b0 = __ldg(bias + cc); b1 = __ldg(bias + cc + 1); }
            *(float2*)(C + (size_t)r * N + cc) =
                make_float2(d[mi][nj][0] + b0, d[mi][nj][1] + b1);
            *(float2*)(C + (size_t)(r + 8) * N + cc) =
                make_float2(d[mi][nj][2] + b0, d[mi][nj][3] + b1);
        }
    }
    #undef PREFETCH
}

// ---------------------------------------------------------------------------
// Flash attention (fp32 FFMA, unchanged from R2)
// ---------------------------------------------------------------------------
__global__ __launch_bounds__(256) void attn_kernel(
    const float* __restrict__ q, const float* __restrict__ kv,
    float* __restrict__ x)
{
    __shared__ float Qt[64][68];
    __shared__ float Kt[64][36];
    __shared__ float Vs[32][68];
    __shared__ float Ps[64][36];

    const int tid = threadIdx.x;
    const int tx  = tid & 15;
    const int ty  = tid >> 4;
    const int bh  = blockIdx.y;
    const int b   = bh >> 4;
    const int h   = bh & 15;
    const int r0  = blockIdx.x * 64;

    const float* Qp = q  + (size_t)(b * SQL + r0) * HID + h * HD;
    const float* Kp = kv + (size_t)b * SKV * (2 * HID) + h * HD;
    const float* Vp = Kp + HID;

    {
        const int row = tid >> 2;
        const int d4  = (tid & 3) * 4;
        #pragma unroll
        for (int p = 0; p < 4; p++) {
            int d = d4 + p * 16;
            float4 v = *(const float4*)(Qp + (size_t)row * HID + d);
            Qt[d + 0][row] = v.x * 0.125f;
            Qt[d + 1][row] = v.y * 0.125f;
            Qt[d + 2][row] = v.z * 0.125f;
            Qt[d + 3][row] = v.w * 0.125f;
        }
    }

    float O[4][4] = {};
    float mrow[4] = {-1e30f, -1e30f, -1e30f, -1e30f};
    float lrow[4] = {};

    const int krow = tid >> 3;
    const int kd4  = (tid & 7) * 4;

    for (int kv0 = 0; kv0 < SKV; kv0 += 32) {
        float4 kr[2], vr[2];
        #pragma unroll
        for (int p = 0; p < 2; p++) {
            int d = kd4 + p * 32;
            kr[p] = *(const float4*)(Kp + (size_t)(kv0 + krow) * (2 * HID) + d);
            vr[p] = *(const float4*)(Vp + (size_t)(kv0 + krow) * (2 * HID) + d);
        }
        __syncthreads();
        #pragma unroll
        for (int p = 0; p < 2; p++) {
            int d = kd4 + p * 32;
            Kt[d + 0][krow] = kr[p].x;
            Kt[d + 1][krow] = kr[p].y;
            Kt[d + 2][krow] = kr[p].z;
            Kt[d + 3][krow] = kr[p].w;
            *(float4*)&Vs[krow][d] = vr[p];
        }
        __syncthreads();

        float s0[4] = {}, s1[4] = {};
        #pragma unroll
        for (int d = 0; d < 64; d++) {
            float4 ra = *(const float4*)&Qt[d][ty * 4];
            float2 rb = *(const float2*)&Kt[d][tx * 2];
            s0[0] += ra.x * rb.x; s1[0] += ra.x * rb.y;
            s0[1] += ra.y * rb.x; s1[1] += ra.y * rb.y;
            s0[2] += ra.z * rb.x; s1[2] += ra.z * rb.y;
            s0[3] += ra.w * rb.x; s1[3] += ra.w * rb.y;
        }

        #pragma unroll
        for (int i = 0; i < 4; i++) {
            float tm = fmaxf(s0[i], s1[i]);
            #pragma unroll
            for (int off = 8; off; off >>= 1)
                tm = fmaxf(tm, __shfl_xor_sync(0xffffffffu, tm, off));
            float mn   = fmaxf(mrow[i], tm);
            float corr = __expf(mrow[i] - mn);
            float p0   = __expf(s0[i] - mn);
            float p1   = __expf(s1[i] - mn);
            float ts   = p0 + p1;
            #pragma unroll
            for (int off = 8; off; off >>= 1)
                ts += __shfl_xor_sync(0xffffffffu, ts, off);
            lrow[i] = lrow[i] * corr + ts;
            mrow[i] = mn;
            O[i][0] *= corr; O[i][1] *= corr; O[i][2] *= corr; O[i][3] *= corr;
            *(float2*)&Ps[ty * 4 + i][tx * 2] = make_float2(p0, p1);
        }
        __syncthreads();

        #pragma unroll
        for (int k = 0; k < 32; k++) {
            float4 v = *(const float4*)&Vs[k][tx * 4];
            #pragma unroll
            for (int i = 0; i < 4; i++) {
                float p = Ps[ty * 4 + i][k];
                O[i][0] += p * v.x; O[i][1] += p * v.y;
                O[i][2] += p * v.z; O[i][3] += p * v.w;
            }
        }
    }

    #pragma unroll
    for (int i = 0; i < 4; i++) {
        float inv = 1.0f / lrow[i];
        float4 o = make_float4(O[i][0] * inv, O[i][1] * inv,
                               O[i][2] * inv, O[i][3] * inv);
        *(float4*)(x + (size_t)(b * SQL + r0 + ty * 4 + i) * HID + h * HD + tx * 4) = o;
    }
}

// ---------------------------------------------------------------------------
extern "C" void kernel_launch(void* const* d_in, const int* in_sizes, int n_in,
                              void* d_out, int out_size)
{
    const float* xq   = (const float*)d_in[0];
    const float* xkv  = (const float*)d_in[1];
    const float* Wq   = (const float*)d_in[2];
    const float* Wkv  = (const float*)d_in[3];
    const float* Wout = (const float*)d_in[4];
    const float* bout = (const float*)d_in[5];
    float* out = (float*)d_out;

    float *qp, *kvp, *xp;
    cudaGetSymbolAddress((void**)&qp,  g_q);
    cudaGetSymbolAddress((void**)&kvp, g_kv);
    cudaGetSymbolAddress((void**)&xp,  g_x);
    void *p_xq, *p_xkv, *p_wq, *p_wkv, *p_wo, *p_x;
    cudaGetSymbolAddress(&p_xq,  s_xq);
    cudaGetSymbolAddress(&p_xkv, s_xkv);
    cudaGetSymbolAddress(&p_wq,  s_wq);
    cudaGetSymbolAddress(&p_wkv, s_wkv);
    cudaGetSymbolAddress(&p_wo,  s_wo);
    cudaGetSymbolAddress(&p_x,   s_x);

    auto sp = [](const float* X, void* S, int n) {
        split_bf16_k<<<(n / 4 + 255) / 256, 256>>>(X, (__nv_bfloat16*)S, n);
    };
    sp(xq,   p_xq,  NB * SQL * HID);
    sp(xkv,  p_xkv, NB * SKV * HID);
    sp(Wq,   p_wq,  HID * HID);
    sp(Wkv,  p_wkv, 2 * HID * HID);
    sp(Wout, p_wo,  HID * HID);

    // q = xq @ Wq^T
    gemm_mma<false><<<dim3(HID / 128, (NB * SQL) / 128), 256>>>(
        (const __nv_bfloat16*)p_xq, (const __nv_bfloat16*)p_wq,
        nullptr, qp, NB * SQL, HID);

    // kv = xkv @ Wkv^T
    gemm_mma<false><<<dim3((2 * HID) / 128, (NB * SKV) / 128), 256>>>(
        (const __nv_bfloat16*)p_xkv, (const __nv_bfloat16*)p_wkv,
        nullptr, kvp, NB * SKV, 2 * HID);

    // attention
    attn_kernel<<<dim3(SQL / 64, NB * NH), 256>>>(qp, kvp, xp);

    // out = x @ Wout^T + bout
    sp(xp, p_x, NB * SQL * HID);
    gemm_mma<true><<<dim3(HID / 128, (NB * SQL) / 128), 256>>>(
        (const __nv_bfloat16*)p_x, (const __nv_bfloat16*)p_wo,
        bout, out, NB * SQL, HID);
}

// round 5
// speedup vs baseline: 2.7679x; 1.7165x over previous
#include <cuda_runtime.h>
#include <cuda_bf16.h>
#include <math.h>
#include <stdint.h>

#define HID 1024
#define NH  16
#define HD  64
#define NB  4
#define SQL 1024
#define SKV 2048

// ---------------- scratch (__device__ globals; no allocs allowed) ----------
__device__ float g_q [(size_t)NB * SQL * HID];          // 16 MB
__device__ float g_kv[(size_t)NB * SKV * 2 * HID];      // 64 MB
// split-bf16: hi in first n elements, lo in next n
__device__ __nv_bfloat16 s_xq [(size_t)2 * NB * SQL * HID];
__device__ __nv_bfloat16 s_xkv[(size_t)2 * NB * SKV * HID];
__device__ __nv_bfloat16 s_wq [(size_t)2 * HID * HID];
__device__ __nv_bfloat16 s_wkv[(size_t)2 * 2 * HID * HID];
__device__ __nv_bfloat16 s_wo [(size_t)2 * HID * HID];
__device__ __nv_bfloat16 s_x  [(size_t)2 * NB * SQL * HID];
__device__ __nv_bfloat16 s_qa [(size_t)2 * NB * SQL * HID];       // split q
__device__ __nv_bfloat16 s_kva[(size_t)2 * NB * SKV * 2 * HID];   // split kv

// ---------------------------------------------------------------------------
static __device__ __forceinline__ uint32_t smem_u32(const void* p) {
    uint32_t a;
    asm("{ .reg .u64 t; cvta.to.shared.u64 t, %1; cvt.u32.u64 %0, t; }"
        : "=r"(a) : "l"(p));
    return a;
}

#define CPA16(dst, src) \
    asm volatile("cp.async.cg.shared.global [%0], [%1], 16;" \
                 :: "r"(dst), "l"(src) : "memory")
#define CPA_COMMIT() asm volatile("cp.async.commit_group;" ::: "memory")
#define CPA_WAIT1()  asm volatile("cp.async.wait_group 1;" ::: "memory")
#define CPA_WAIT0()  asm volatile("cp.async.wait_group 0;" ::: "memory")

#define LDM4(r0, r1, r2, r3, addr) \
    asm volatile("ldmatrix.sync.aligned.m8n8.x4.shared.b16 {%0,%1,%2,%3}, [%4];" \
                 : "=r"(r0), "=r"(r1), "=r"(r2), "=r"(r3) : "r"(addr))
#define LDM4T(r0, r1, r2, r3, addr) \
    asm volatile("ldmatrix.sync.aligned.m8n8.x4.trans.shared.b16 {%0,%1,%2,%3}, [%4];" \
                 : "=r"(r0), "=r"(r1), "=r"(r2), "=r"(r3) : "r"(addr))

#define MMAF(d, a, b0, b1) \
    asm volatile("mma.sync.aligned.m16n8k16.row.col.f32.bf16.bf16.f32 " \
                 "{%0,%1,%2,%3}, {%4,%5,%6,%7}, {%8,%9}, {%0,%1,%2,%3};" \
                 : "+f"((d)[0]), "+f"((d)[1]), "+f"((d)[2]), "+f"((d)[3]) \
                 : "r"((a)[0]), "r"((a)[1]), "r"((a)[2]), "r"((a)[3]), \
                   "r"(b0), "r"(b1))

// GEMM smem swizzle: 32-bf16 (64B) rows, 4 chunks
static __device__ __forceinline__ uint32_t sw(int r, int c) {
    return (uint32_t)(r * 64 + ((c ^ ((r >> 1) & 3)) * 16));
}
// attention smem swizzle: 64-bf16 (128B) rows, 8 chunks
static __device__ __forceinline__ uint32_t swz(int r, int c) {
    return (uint32_t)(r * 128 + ((c ^ (r & 7)) * 16));
}

static __device__ __forceinline__ uint32_t pack_bf2(float lo, float hi) {
    __nv_bfloat162 t = __float22bfloat162_rn(make_float2(lo, hi));
    return *(uint32_t*)&t;
}
static __device__ __forceinline__ float2 unpack_bf2(uint32_t u) {
    __nv_bfloat162 t = *(__nv_bfloat162*)&u;
    return __bfloat1622float2(t);   // .x = low half
}

// ---------------------------------------------------------------------------
// split fp32 -> (hi, lo) bf16
// ---------------------------------------------------------------------------
__global__ void split_bf16_k(const float* __restrict__ X,
                             __nv_bfloat16* __restrict__ S, int n)
{
    int i = (blockIdx.x * blockDim.x + threadIdx.x) * 4;
    if (i >= n) return;
    float4 x = *(const float4*)(X + i);
    float v[4] = {x.x, x.y, x.z, x.w};
    __nv_bfloat16 h[4], l[4];
    #pragma unroll
    for (int j = 0; j < 4; j++) {
        h[j] = __float2bfloat16(v[j]);
        l[j] = __float2bfloat16(v[j] - __bfloat162float(h[j]));
    }
    *(__nv_bfloat162*)(S + i)         = __halves2bfloat162(h[0], h[1]);
    *(__nv_bfloat162*)(S + i + 2)     = __halves2bfloat162(h[2], h[3]);
    *(__nv_bfloat162*)(S + n + i)     = __halves2bfloat162(l[0], l[1]);
    *(__nv_bfloat162*)(S + n + i + 2) = __halves2bfloat162(l[2], l[3]);
}

// ---------------------------------------------------------------------------
// Split-bf16 NT GEMM via mma.sync (unchanged from R4)
// ---------------------------------------------------------------------------
template<bool BIAS>
__global__ __launch_bounds__(256, 2) void gemm_mma(
    const __nv_bfloat16* __restrict__ A, const __nv_bfloat16* __restrict__ B,
    const float* __restrict__ bias, float* __restrict__ C, int M, int N)
{
    __shared__ __align__(1024) char smem[4 * 8192];

    const int tid  = threadIdx.x;
    const int wid  = tid >> 5;
    const int lane = tid & 31;
    const int m0   = blockIdx.y * 128;
    const int n0   = blockIdx.x * 128;
    const int wm   = wid & 1;
    const int wn   = wid >> 1;

    const uint32_t sb = smem_u32(smem);
    const size_t MK = (size_t)M * HID, NK = (size_t)N * HID;
    const int NIT = 96;

    #define PREFETCH(it, s) do {                                              \
        int _seg = (it) >> 5, _kb = (it) & 31;                                \
        const __nv_bfloat16* _Ab = A + (_seg == 2 ? MK : 0);                  \
        const __nv_bfloat16* _Bb = B + (_seg == 1 ? NK : 0);                  \
        uint32_t _sa = sb + (s) * 8192;                                       \
        uint32_t _sb2 = sb + 16384 + (s) * 8192;                              \
        _Pragma("unroll")                                                     \
        for (int _q = 0; _q < 2; _q++) {                                      \
            int _ch = tid * 2 + _q;                                           \
            int _r = _ch >> 2, _c = _ch & 3;                                  \
            CPA16(_sa  + sw(_r, _c), _Ab + (size_t)(m0 + _r) * HID + _kb * 32 + _c * 8); \
            CPA16(_sb2 + sw(_r, _c), _Bb + (size_t)(n0 + _r) * HID + _kb * 32 + _c * 8); \
        }                                                                     \
        CPA_COMMIT();                                                         \
    } while (0)

    float d[4][4][4] = {};
    PREFETCH(0, 0);

    for (int it = 0; it < NIT; it++) {
        const int s = it & 1;
        if (it + 1 < NIT) { PREFETCH(it + 1, s ^ 1); CPA_WAIT1(); }
        else              { CPA_WAIT0(); }
        __syncthreads();

        const uint32_t sa  = sb + s * 8192;
        const uint32_t sbm = sb + 16384 + s * 8192;

        #pragma unroll
        for (int ks = 0; ks < 2; ks++) {
            uint32_t a[4][4];
            #pragma unroll
            for (int mi = 0; mi < 4; mi++) {
                int r = wm * 64 + mi * 16 + ((lane >> 3) & 1) * 8 + (lane & 7);
                int c = ks * 2 + ((lane >> 4) & 1);
                LDM4(a[mi][0], a[mi][1], a[mi][2], a[mi][3], sa + sw(r, c));
            }
            uint32_t b[4][2];
            #pragma unroll
            for (int ni = 0; ni < 2; ni++) {
                int r = wn * 32 + ni * 16 + ((lane >> 4) & 1) * 8 + (lane & 7);
                int c = ks * 2 + ((lane >> 3) & 1);
                uint32_t r0, r1, r2, r3;
                LDM4(r0, r1, r2, r3, sbm + sw(r, c));
                b[ni * 2][0] = r0; b[ni * 2][1] = r1;
                b[ni * 2 + 1][0] = r2; b[ni * 2 + 1][1] = r3;
            }
            #pragma unroll
            for (int mi = 0; mi < 4; mi++)
                #pragma unroll
                for (int nj = 0; nj < 4; nj++)
                    MMAF(d[mi][nj], a[mi], b[nj][0], b[nj][1]);
        }
        __syncthreads();
    }

    const int row0 = m0 + wm * 64 + (lane >> 2);
    const int col0 = n0 + wn * 32 + (lane & 3) * 2;
    #pragma unroll
    for (int mi = 0; mi < 4; mi++) {
        #pragma unroll
        for (int nj = 0; nj < 4; nj++) {
            int r = row0 + mi * 16;
            int cc = col0 + nj * 8;
            float b0 = 0.f, b1 = 0.f;
            if (BIAS) { b0 = __ldg(bias + cc); b1 = __ldg(bias + cc + 1); }
            *(float2*)(C + (size_t)r * N + cc) =
                make_float2(d[mi][nj][0] + b0, d[mi][nj][1] + b1);
            *(float2*)(C + (size_t)(r + 8) * N + cc) =
                make_float2(d[mi][nj][2] + b0, d[mi][nj][3] + b1);
        }
    }
    #undef PREFETCH
}

// ---------------------------------------------------------------------------
// Split-bf16 mma.sync flash attention.
// Block: 128 q-rows x one (b,h); KV tiles of 64; 8 warps, warp = 16 rows.
// S = qh*kh + qh*kl + ql*kh ; O += ph*vh + ph*vl + pl*vh.
// Output written directly as split-bf16 into s_x.
// ---------------------------------------------------------------------------
#define AT_SMEM 98304

__global__ __launch_bounds__(256, 1) void attn_mma(
    const __nv_bfloat16* __restrict__ q,
    const __nv_bfloat16* __restrict__ kvs,
    __nv_bfloat16* __restrict__ xout)
{
    extern __shared__ __align__(1024) char smem[];
    const uint32_t sb  = smem_u32(smem);
    const uint32_t sQh = sb, sQl = sb + 16384;

    const int tid  = threadIdx.x;
    const int lane = tid & 31;
    const int w    = tid >> 5;
    const int lr   = lane & 7;
    const int sel  = lane >> 3;

    const int qt = blockIdx.x;
    const int bh = blockIdx.y;
    const int b  = bh >> 4;
    const int h  = bh & 15;

    const size_t NQ  = (size_t)NB * SQL * HID;
    const size_t NKV = (size_t)NB * SKV * 2 * HID;

    const __nv_bfloat16* Qb = q   + (size_t)(b * SQL + qt * 128) * HID + h * HD;
    const __nv_bfloat16* Kb = kvs + (size_t)b * SKV * 2 * HID + h * HD;

    // ---- issue Q (hi+lo) + KV tile 0, then KV tile 1 ----
    {
        #pragma unroll
        for (int qq = 0; qq < 4; qq++) {
            int ch = tid * 4 + qq;
            int r = ch >> 3, c = ch & 7;
            const __nv_bfloat16* src = Qb + (size_t)r * HID + c * 8;
            CPA16(sQh + swz(r, c), src);
            CPA16(sQl + swz(r, c), src + NQ);
        }
    }
    #define ISSUE_KV(t, st) do {                                              \
        int _kv0 = (t) * 64;                                                  \
        _Pragma("unroll")                                                     \
        for (int _qq = 0; _qq < 2; _qq++) {                                   \
            int _ch = tid * 2 + _qq;                                          \
            int _r = _ch >> 3, _c = _ch & 7;                                  \
            const __nv_bfloat16* _k = Kb + (size_t)(_kv0 + _r) * 2048 + _c * 8; \
            uint32_t _d = swz(_r, _c);                                        \
            CPA16((st) +         _d, _k);                                     \
            CPA16((st) + 8192  + _d, _k + NKV);                               \
            CPA16((st) + 16384 + _d, _k + HID);                               \
            CPA16((st) + 24576 + _d, _k + HID + NKV);                         \
        }                                                                     \
        CPA_COMMIT();                                                         \
    } while (0)

    CPA_COMMIT();                       // group: Q + (nothing else yet)
    ISSUE_KV(0, sb + 32768);            // group: KV0
    ISSUE_KV(1, sb + 65536);            // group: KV1
    CPA_WAIT1();                        // Q + KV0 done
    __syncthreads();

    // ---- Q fragments (persistent) ----
    uint32_t QAh[4][4], QAl[4][4];
    {
        const int r0 = w * 16;
        #pragma unroll
        for (int kk = 0; kk < 4; kk++) {
            int row = r0 + lr + ((sel & 1) ? 8 : 0);
            int ch  = 2 * kk + (sel >> 1);
            LDM4(QAh[kk][0], QAh[kk][1], QAh[kk][2], QAh[kk][3], sQh + swz(row, ch));
            LDM4(QAl[kk][0], QAl[kk][1], QAl[kk][2], QAl[kk][3], sQl + swz(row, ch));
        }
    }

    float O[8][4] = {};
    float m0 = -1e30f, m1 = -1e30f, l0 = 0.f, l1 = 0.f;

    #pragma unroll 1
    for (int kt = 0; kt < 32; kt++) {
        const uint32_t st  = sb + 32768 + (kt & 1) * 32768;
        const uint32_t sKh = st, sKl = st + 8192;
        const uint32_t sVh = st + 16384, sVl = st + 24576;

        float S[8][4];
        #pragma unroll
        for (int g = 0; g < 8; g++)
            S[g][0] = S[g][1] = S[g][2] = S[g][3] = 0.f;

        // ---- S = qh*kh + ql*kh ----
        #pragma unroll
        for (int kk = 0; kk < 4; kk++) {
            uint32_t bk[4][4];
            #pragma unroll
            for (int jp = 0; jp < 4; jp++) {
                int row = jp * 16 + lr + ((sel & 2) ? 8 : 0);
                int ch  = 2 * kk + (sel & 1);
                LDM4(bk[jp][0], bk[jp][1], bk[jp][2], bk[jp][3], sKh + swz(row, ch));
            }
            #pragma unroll
            for (int jp = 0; jp < 4; jp++) {
                MMAF(S[2*jp],   QAh[kk], bk[jp][0], bk[jp][1]);
                MMAF(S[2*jp+1], QAh[kk], bk[jp][2], bk[jp][3]);
                MMAF(S[2*jp],   QAl[kk], bk[jp][0], bk[jp][1]);
                MMAF(S[2*jp+1], QAl[kk], bk[jp][2], bk[jp][3]);
            }
        }
        // ---- S += qh*kl ----
        #pragma unroll
        for (int kk = 0; kk < 4; kk++) {
            uint32_t bk[4][4];
            #pragma unroll
            for (int jp = 0; jp < 4; jp++) {
                int row = jp * 16 + lr + ((sel & 2) ? 8 : 0);
                int ch  = 2 * kk + (sel & 1);
                LDM4(bk[jp][0], bk[jp][1], bk[jp][2], bk[jp][3], sKl + swz(row, ch));
            }
            #pragma unroll
            for (int jp = 0; jp < 4; jp++) {
                MMAF(S[2*jp],   QAh[kk], bk[jp][0], bk[jp][1]);
                MMAF(S[2*jp+1], QAh[kk], bk[jp][2], bk[jp][3]);
            }
        }

        // ---- online softmax (quad-local rows) ----
        float mx0 = -1e30f, mx1 = -1e30f;
        #pragma unroll
        for (int g = 0; g < 8; g++) {
            S[g][0] *= 0.125f; S[g][1] *= 0.125f;
            S[g][2] *= 0.125f; S[g][3] *= 0.125f;
            mx0 = fmaxf(mx0, fmaxf(S[g][0], S[g][1]));
            mx1 = fmaxf(mx1, fmaxf(S[g][2], S[g][3]));
        }
        mx0 = fmaxf(mx0, __shfl_xor_sync(0xffffffffu, mx0, 1));
        mx0 = fmaxf(mx0, __shfl_xor_sync(0xffffffffu, mx0, 2));
        mx1 = fmaxf(mx1, __shfl_xor_sync(0xffffffffu, mx1, 1));
        mx1 = fmaxf(mx1, __shfl_xor_sync(0xffffffffu, mx1, 2));
        float mn0 = fmaxf(m0, mx0), mn1 = fmaxf(m1, mx1);
        float c0 = __expf(m0 - mn0), c1 = __expf(m1 - mn1);
        float sum0 = 0.f, sum1 = 0.f;
        #pragma unroll
        for (int g = 0; g < 8; g++) {
            S[g][0] = __expf(S[g][0] - mn0);
            S[g][1] = __expf(S[g][1] - mn0);
            S[g][2] = __expf(S[g][2] - mn1);
            S[g][3] = __expf(S[g][3] - mn1);
            sum0 += S[g][0] + S[g][1];
            sum1 += S[g][2] + S[g][3];
        }
        sum0 += __shfl_xor_sync(0xffffffffu, sum0, 1);
        sum0 += __shfl_xor_sync(0xffffffffu, sum0, 2);
        sum1 += __shfl_xor_sync(0xffffffffu, sum1, 1);
        sum1 += __shfl_xor_sync(0xffffffffu, sum1, 2);
        l0 = l0 * c0 + sum0;  l1 = l1 * c1 + sum1;
        m0 = mn0;  m1 = mn1;
        #pragma unroll
        for (int g = 0; g < 8; g++) {
            O[g][0] *= c0; O[g][1] *= c0;
            O[g][2] *= c1; O[g][3] *= c1;
        }

        // ---- O += ph*vh + pl*vh + ph*vl ----
        #pragma unroll
        for (int kk = 0; kk < 4; kk++) {
            uint32_t pah[4], pal[4];
            {
                float* A0 = S[2*kk];
                float* A1 = S[2*kk+1];
                pah[0] = pack_bf2(A0[0], A0[1]);
                pah[1] = pack_bf2(A0[2], A0[3]);
                pah[2] = pack_bf2(A1[0], A1[1]);
                pah[3] = pack_bf2(A1[2], A1[3]);
                float2 f0 = unpack_bf2(pah[0]), f1 = unpack_bf2(pah[1]);
                float2 f2 = unpack_bf2(pah[2]), f3 = unpack_bf2(pah[3]);
                pal[0] = pack_bf2(A0[0] - f0.x, A0[1] - f0.y);
                pal[1] = pack_bf2(A0[2] - f1.x, A0[3] - f1.y);
                pal[2] = pack_bf2(A1[0] - f2.x, A1[1] - f2.y);
                pal[3] = pack_bf2(A1[2] - f3.x, A1[3] - f3.y);
            }
            uint32_t bv[4][4];
            #pragma unroll
            for (int jp = 0; jp < 4; jp++) {
                int row = kk * 16 + lr + ((sel & 1) ? 8 : 0);
                int ch  = 2 * jp + (sel >> 1);
                LDM4T(bv[jp][0], bv[jp][1], bv[jp][2], bv[jp][3], sVh + swz(row, ch));
            }
            #pragma unroll
            for (int jp = 0; jp < 4; jp++) {
                MMAF(O[2*jp],   pah, bv[jp][0], bv[jp][1]);
                MMAF(O[2*jp+1], pah, bv[jp][2], bv[jp][3]);
                MMAF(O[2*jp],   pal, bv[jp][0], bv[jp][1]);
                MMAF(O[2*jp+1], pal, bv[jp][2], bv[jp][3]);
            }
            #pragma unroll
            for (int jp = 0; jp < 4; jp++) {
                int row = kk * 16 + lr + ((sel & 1) ? 8 : 0);
                int ch  = 2 * jp + (sel >> 1);
                LDM4T(bv[jp][0], bv[jp][1], bv[jp][2], bv[jp][3], sVl + swz(row, ch));
            }
            #pragma unroll
            for (int jp = 0; jp < 4; jp++) {
                MMAF(O[2*jp],   pah, bv[jp][0], bv[jp][1]);
                MMAF(O[2*jp+1], pah, bv[jp][2], bv[jp][3]);
            }
        }

        // ---- pipeline advance ----
        __syncthreads();
        if (kt + 2 < 32) ISSUE_KV(kt + 2, sb + 32768 + (kt & 1) * 32768);
        if (kt + 1 < 32) {
            if (kt + 2 < 32) CPA_WAIT1(); else CPA_WAIT0();
            __syncthreads();
        }
    }
    #undef ISSUE_KV

    // ---- epilogue: write split-bf16 x directly ----
    {
        float inv0 = 1.f / l0, inv1 = 1.f / l1;
        int row = b * SQL + qt * 128 + w * 16 + (lane >> 2);
        size_t base = (size_t)row * HID + h * HD + (lane & 3) * 2;
        #pragma unroll
        for (int g = 0; g < 8; g++) {
            float x0 = O[g][0] * inv0, x1 = O[g][1] * inv0;
            float y0 = O[g][2] * inv1, y1 = O[g][3] * inv1;
            __nv_bfloat16 h0 = __float2bfloat16(x0), h1 = __float2bfloat16(x1);
            __nv_bfloat16 g0 = __float2bfloat16(y0), g1 = __float2bfloat16(y1);
            *(__nv_bfloat162*)(xout + base + 8 * g) = __halves2bfloat162(h0, h1);
            *(__nv_bfloat162*)(xout + NQ + base + 8 * g) =
                __halves2bfloat162(__float2bfloat16(x0 - __bfloat162float(h0)),
                                   __float2bfloat16(x1 - __bfloat162float(h1)));
            *(__nv_bfloat162*)(xout + base + 8 * HID + 8 * g) = __halves2bfloat162(g0, g1);
            *(__nv_bfloat162*)(xout + NQ + base + 8 * HID + 8 * g) =
                __halves2bfloat162(__float2bfloat16(y0 - __bfloat162float(g0)),
                                   __float2bfloat16(y1 - __bfloat162float(g1)));
        }
    }
}

// ---------------------------------------------------------------------------
extern "C" void kernel_launch(void* const* d_in, const int* in_sizes, int n_in,
                              void* d_out, int out_size)
{
    const float* xq   = (const float*)d_in[0];
    const float* xkv  = (const float*)d_in[1];
    const float* Wq   = (const float*)d_in[2];
    const float* Wkv  = (const float*)d_in[3];
    const float* Wout = (const float*)d_in[4];
    const float* bout = (const float*)d_in[5];
    float* out = (float*)d_out;

    float *qp, *kvp;
    cudaGetSymbolAddress((void**)&qp,  g_q);
    cudaGetSymbolAddress((void**)&kvp, g_kv);
    void *p_xq, *p_xkv, *p_wq, *p_wkv, *p_wo, *p_x, *p_qa, *p_kva;
    cudaGetSymbolAddress(&p_xq,  s_xq);
    cudaGetSymbolAddress(&p_xkv, s_xkv);
    cudaGetSymbolAddress(&p_wq,  s_wq);
    cudaGetSymbolAddress(&p_wkv, s_wkv);
    cudaGetSymbolAddress(&p_wo,  s_wo);
    cudaGetSymbolAddress(&p_x,   s_x);
    cudaGetSymbolAddress(&p_qa,  s_qa);
    cudaGetSymbolAddress(&p_kva, s_kva);

    cudaFuncSetAttribute(attn_mma,
        cudaFuncAttributeMaxDynamicSharedMemorySize, AT_SMEM);

    auto sp = [](const float* X, void* S, int n) {
        split_bf16_k<<<(n / 4 + 255) / 256, 256>>>(X, (__nv_bfloat16*)S, n);
    };
    sp(xq,   p_xq,  NB * SQL * HID);
    sp(xkv,  p_xkv, NB * SKV * HID);
    sp(Wq,   p_wq,  HID * HID);
    sp(Wkv,  p_wkv, 2 * HID * HID);
    sp(Wout, p_wo,  HID * HID);

    // q = xq @ Wq^T
    gemm_mma<false><<<dim3(HID / 128, (NB * SQL) / 128), 256>>>(
        (const __nv_bfloat16*)p_xq, (const __nv_bfloat16*)p_wq,
        nullptr, qp, NB * SQL, HID);

    // kv = xkv @ Wkv^T
    gemm_mma<false><<<dim3((2 * HID) / 128, (NB * SKV) / 128), 256>>>(
        (const __nv_bfloat16*)p_xkv, (const __nv_bfloat16*)p_wkv,
        nullptr, kvp, NB * SKV, 2 * HID);

    // split q and kv for tensor-core attention
    sp(qp,  p_qa,  NB * SQL * HID);
    sp(kvp, p_kva, NB * SKV * 2 * HID);

    // attention (writes split-bf16 x directly)
    attn_mma<<<dim3(SQL / 128, NB * NH), 256, AT_SMEM>>>(
        (const __nv_bfloat16*)p_qa, (const __nv_bfloat16*)p_kva,
        (__nv_bfloat16*)p_x);

    // out = x @ Wout^T + bout
    gemm_mma<true><<<dim3(HID / 128, (NB * SQL) / 128), 256>>>(
        (const __nv_bfloat16*)p_x, (const __nv_bfloat16*)p_wo,
        bout, out, NB * SQL, HID);
}

// round 6
// speedup vs baseline: 2.8502x; 1.0297x over previous
#include <cuda_runtime.h>
#include <cuda_bf16.h>
#include <math.h>
#include <stdint.h>

#define HID 1024
#define NH  16
#define HD  64
#define NB  4
#define SQL 1024
#define SKV 2048

// ---------------- scratch (__device__ globals; no allocs allowed) ----------
// split-bf16: hi in first n elements, lo in next n
__device__ __nv_bfloat16 s_xq [(size_t)2 * NB * SQL * HID];
__device__ __nv_bfloat16 s_xkv[(size_t)2 * NB * SKV * HID];
__device__ __nv_bfloat16 s_wq [(size_t)2 * HID * HID];
__device__ __nv_bfloat16 s_wkv[(size_t)2 * 2 * HID * HID];
__device__ __nv_bfloat16 s_wo [(size_t)2 * HID * HID];
__device__ __nv_bfloat16 s_x  [(size_t)2 * NB * SQL * HID];
__device__ __nv_bfloat16 s_qa [(size_t)2 * NB * SQL * HID];       // split q
__device__ __nv_bfloat16 s_kva[(size_t)2 * NB * SKV * 2 * HID];   // split kv

// ---------------------------------------------------------------------------
static __device__ __forceinline__ uint32_t smem_u32(const void* p) {
    uint32_t a;
    asm("{ .reg .u64 t; cvta.to.shared.u64 t, %1; cvt.u32.u64 %0, t; }"
        : "=r"(a) : "l"(p));
    return a;
}

#define CPA16(dst, src) \
    asm volatile("cp.async.cg.shared.global [%0], [%1], 16;" \
                 :: "r"(dst), "l"(src) : "memory")
#define CPA_COMMIT() asm volatile("cp.async.commit_group;" ::: "memory")
#define CPA_WAIT2()  asm volatile("cp.async.wait_group 2;" ::: "memory")
#define CPA_WAIT1()  asm volatile("cp.async.wait_group 1;" ::: "memory")
#define CPA_WAIT0()  asm volatile("cp.async.wait_group 0;" ::: "memory")

#define LDM4(r0, r1, r2, r3, addr) \
    asm volatile("ldmatrix.sync.aligned.m8n8.x4.shared.b16 {%0,%1,%2,%3}, [%4];" \
                 : "=r"(r0), "=r"(r1), "=r"(r2), "=r"(r3) : "r"(addr))
#define LDM4T(r0, r1, r2, r3, addr) \
    asm volatile("ldmatrix.sync.aligned.m8n8.x4.trans.shared.b16 {%0,%1,%2,%3}, [%4];" \
                 : "=r"(r0), "=r"(r1), "=r"(r2), "=r"(r3) : "r"(addr))

#define MMAF(d, a, b0, b1) \
    asm volatile("mma.sync.aligned.m16n8k16.row.col.f32.bf16.bf16.f32 " \
                 "{%0,%1,%2,%3}, {%4,%5,%6,%7}, {%8,%9}, {%0,%1,%2,%3};" \
                 : "+f"((d)[0]), "+f"((d)[1]), "+f"((d)[2]), "+f"((d)[3]) \
                 : "r"((a)[0]), "r"((a)[1]), "r"((a)[2]), "r"((a)[3]), \
                   "r"(b0), "r"(b1))

// GEMM smem swizzle: 32-bf16 (64B) rows, 4 chunks of 16B
static __device__ __forceinline__ uint32_t sw(int r, int c) {
    return (uint32_t)(r * 64 + ((c ^ ((r >> 1) & 3)) * 16));
}
// attention smem swizzle: 64-bf16 (128B) rows, 8 chunks
static __device__ __forceinline__ uint32_t swz(int r, int c) {
    return (uint32_t)(r * 128 + ((c ^ (r & 7)) * 16));
}

static __device__ __forceinline__ uint32_t pack_bf2(float lo, float hi) {
    __nv_bfloat162 t = __float22bfloat162_rn(make_float2(lo, hi));
    return *(uint32_t*)&t;
}
static __device__ __forceinline__ float2 unpack_bf2(uint32_t u) {
    __nv_bfloat162 t = *(__nv_bfloat162*)&u;
    return __bfloat1622float2(t);
}

// ---------------------------------------------------------------------------
// split fp32 -> (hi, lo) bf16
// ---------------------------------------------------------------------------
__global__ void split_bf16_k(const float* __restrict__ X,
                             __nv_bfloat16* __restrict__ S, int n)
{
    int i = (blockIdx.x * blockDim.x + threadIdx.x) * 4;
    if (i >= n) return;
    float4 x = *(const float4*)(X + i);
    float v[4] = {x.x, x.y, x.z, x.w};
    __nv_bfloat16 h[4], l[4];
    #pragma unroll
    for (int j = 0; j < 4; j++) {
        h[j] = __float2bfloat16(v[j]);
        l[j] = __float2bfloat16(v[j] - __bfloat162float(h[j]));
    }
    *(__nv_bfloat162*)(S + i)         = __halves2bfloat162(h[0], h[1]);
    *(__nv_bfloat162*)(S + i + 2)     = __halves2bfloat162(h[2], h[3]);
    *(__nv_bfloat162*)(S + n + i)     = __halves2bfloat162(l[0], l[1]);
    *(__nv_bfloat162*)(S + n + i + 2) = __halves2bfloat162(l[2], l[3]);
}

// ---------------------------------------------------------------------------
// Split-bf16 NT GEMM v2 via mma.sync.
// Block 256x128, BK=32, 8 warps (4m x 2n), warp tile 64x64.
// 4-stage cp.async pipeline, 96KB dynamic smem.
// OMODE: 0 = fp32 out, 1 = fp32 + bias, 2 = split-bf16 out (hi @C, lo @C+M*N).
// ---------------------------------------------------------------------------
#define GSTAGE_BYTES 24576             // A 16KB + B 8KB
#define GSMEM (4 * GSTAGE_BYTES)       // 98304

template<int OMODE>
__global__ __launch_bounds__(256) void gemm_mma2(
    const __nv_bfloat16* __restrict__ A, const __nv_bfloat16* __restrict__ B,
    const float* __restrict__ bias, void* __restrict__ Cv, int M, int N)
{
    extern __shared__ __align__(1024) char smem[];
    const uint32_t sb = smem_u32(smem);

    const int tid  = threadIdx.x;
    const int wid  = tid >> 5;
    const int lane = tid & 31;
    const int m0   = blockIdx.y * 256;
    const int n0   = blockIdx.x * 128;
    const int wm   = wid & 3;           // 4 warp rows (64 each)
    const int wn   = wid >> 2;          // 2 warp cols (64 each)

    const size_t MK = (size_t)M * HID, NK = (size_t)N * HID;
    const int NIT = 96;                 // 3 segments x 32 k-blocks

    #define PRE(it, s) do {                                                   \
        int _seg = (it) >> 5, _kb = (it) & 31;                                \
        const __nv_bfloat16* _Ab = A + (_seg == 2 ? MK : 0);                  \
        const __nv_bfloat16* _Bb = B + (_seg == 1 ? NK : 0);                  \
        uint32_t _ba = sb + (s) * GSTAGE_BYTES;                               \
        _Pragma("unroll")                                                     \
        for (int _q = 0; _q < 4; _q++) {                                      \
            int _ch = tid + _q * 256;                                         \
            int _r = _ch >> 2, _c = _ch & 3;                                  \
            CPA16(_ba + sw(_r, _c),                                           \
                  _Ab + (size_t)(m0 + _r) * HID + _kb * 32 + _c * 8);         \
        }                                                                     \
        _Pragma("unroll")                                                     \
        for (int _q = 0; _q < 2; _q++) {                                      \
            int _ch = tid + _q * 256;                                         \
            int _r = _ch >> 2, _c = _ch & 3;                                  \
            CPA16(_ba + 16384 + sw(_r, _c),                                   \
                  _Bb + (size_t)(n0 + _r) * HID + _kb * 32 + _c * 8);         \
        }                                                                     \
        CPA_COMMIT();                                                         \
    } while (0)

    float d[4][8][4] = {};

    PRE(0, 0); PRE(1, 1); PRE(2, 2);

    #pragma unroll 1
    for (int it = 0; it < NIT; it++) {
        if (it <= NIT - 3)      CPA_WAIT2();
        else if (it == NIT - 2) CPA_WAIT1();
        else                    CPA_WAIT0();
        __syncthreads();

        const uint32_t sa  = sb + (it & 3) * GSTAGE_BYTES;
        const uint32_t sbm = sa + 16384;

        #pragma unroll
        for (int ks = 0; ks < 2; ks++) {
            uint32_t a[4][4];
            #pragma unroll
            for (int mi = 0; mi < 4; mi++) {
                int r = wm * 64 + mi * 16 + (lane & 15);
                int c = ks * 2 + ((lane >> 4) & 1);
                LDM4(a[mi][0], a[mi][1], a[mi][2], a[mi][3], sa + sw(r, c));
            }
            uint32_t b[8][2];
            #pragma unroll
            for (int ni = 0; ni < 4; ni++) {
                int r = wn * 64 + ni * 16 + ((lane >> 4) & 1) * 8 + (lane & 7);
                int c = ks * 2 + ((lane >> 3) & 1);
                uint32_t r0, r1, r2, r3;
                LDM4(r0, r1, r2, r3, sbm + sw(r, c));
                b[ni * 2][0] = r0;     b[ni * 2][1] = r1;
                b[ni * 2 + 1][0] = r2; b[ni * 2 + 1][1] = r3;
            }
            #pragma unroll
            for (int mi = 0; mi < 4; mi++)
                #pragma unroll
                for (int nj = 0; nj < 8; nj++)
                    MMAF(d[mi][nj], a[mi], b[nj][0], b[nj][1]);
        }
        __syncthreads();
        if (it + 3 < NIT) PRE(it + 3, (it + 3) & 3);
    }
    #undef PRE

    // ---- epilogue ----
    const int row0 = m0 + wm * 64 + (lane >> 2);
    const int col0 = n0 + wn * 64 + (lane & 3) * 2;

    if (OMODE < 2) {
        float* C = (float*)Cv;
        #pragma unroll
        for (int mi = 0; mi < 4; mi++) {
            #pragma unroll
            for (int nj = 0; nj < 8; nj++) {
                int r = row0 + mi * 16;
                int cc = col0 + nj * 8;
                float b0 = 0.f, b1 = 0.f;
                if (OMODE == 1) { b0 = __ldg(bias + cc); b1 = __ldg(bias + cc + 1); }
                *(float2*)(C + (size_t)r * N + cc) =
                    make_float2(d[mi][nj][0] + b0, d[mi][nj][1] + b1);
                *(float2*)(C + (size_t)(r + 8) * N + cc) =
                    make_float2(d[mi][nj][2] + b0, d[mi][nj][3] + b1);
            }
        }
    } else {
        __nv_bfloat16* C = (__nv_bfloat16*)Cv;
        const size_t MN = (size_t)M * N;
        #pragma unroll
        for (int mi = 0; mi < 4; mi++) {
            #pragma unroll
            for (int nj = 0; nj < 8; nj++) {
                int r = row0 + mi * 16;
                int cc = col0 + nj * 8;
                #pragma unroll
                for (int half = 0; half < 2; half++) {
                    float v0 = d[mi][nj][half * 2];
                    float v1 = d[mi][nj][half * 2 + 1];
                    size_t off = (size_t)(r + half * 8) * N + cc;
                    __nv_bfloat16 h0 = __float2bfloat16(v0);
                    __nv_bfloat16 h1 = __float2bfloat16(v1);
                    *(__nv_bfloat162*)(C + off) = __halves2bfloat162(h0, h1);
                    *(__nv_bfloat162*)(C + MN + off) = __halves2bfloat162(
                        __float2bfloat16(v0 - __bfloat162float(h0)),
                        __float2bfloat16(v1 - __bfloat162float(h1)));
                }
            }
        }
    }
}

// ---------------------------------------------------------------------------
// Split-bf16 mma.sync flash attention (unchanged from R5).
// ---------------------------------------------------------------------------
#define AT_SMEM 98304

__global__ __launch_bounds__(256, 1) void attn_mma(
    const __nv_bfloat16* __restrict__ q,
    const __nv_bfloat16* __restrict__ kvs,
    __nv_bfloat16* __restrict__ xout)
{
    extern __shared__ __align__(1024) char smem[];
    const uint32_t sb  = smem_u32(smem);
    const uint32_t sQh = sb, sQl = sb + 16384;

    const int tid  = threadIdx.x;
    const int lane = tid & 31;
    const int w    = tid >> 5;
    const int lr   = lane & 7;
    const int sel  = lane >> 3;

    const int qt = blockIdx.x;
    const int bh = blockIdx.y;
    const int b  = bh >> 4;
    const int h  = bh & 15;

    const size_t NQ  = (size_t)NB * SQL * HID;
    const size_t NKV = (size_t)NB * SKV * 2 * HID;

    const __nv_bfloat16* Qb = q   + (size_t)(b * SQL + qt * 128) * HID + h * HD;
    const __nv_bfloat16* Kb = kvs + (size_t)b * SKV * 2 * HID + h * HD;

    {
        #pragma unroll
        for (int qq = 0; qq < 4; qq++) {
            int ch = tid * 4 + qq;
            int r = ch >> 3, c = ch & 7;
            const __nv_bfloat16* src = Qb + (size_t)r * HID + c * 8;
            CPA16(sQh + swz(r, c), src);
            CPA16(sQl + swz(r, c), src + NQ);
        }
    }
    #define ISSUE_KV(t, st) do {                                              \
        int _kv0 = (t) * 64;                                                  \
        _Pragma("unroll")                                                     \
        for (int _qq = 0; _qq < 2; _qq++) {                                   \
            int _ch = tid * 2 + _qq;                                          \
            int _r = _ch >> 3, _c = _ch & 7;                                  \
            const __nv_bfloat16* _k = Kb + (size_t)(_kv0 + _r) * 2048 + _c * 8; \
            uint32_t _d = swz(_r, _c);                                        \
            CPA16((st) +         _d, _k);                                     \
            CPA16((st) + 8192  + _d, _k + NKV);                               \
            CPA16((st) + 16384 + _d, _k + HID);                               \
            CPA16((st) + 24576 + _d, _k + HID + NKV);                         \
        }                                                                     \
        CPA_COMMIT();                                                         \
    } while (0)

    CPA_COMMIT();
    ISSUE_KV(0, sb + 32768);
    ISSUE_KV(1, sb + 65536);
    CPA_WAIT1();
    __syncthreads();

    uint32_t QAh[4][4], QAl[4][4];
    {
        const int r0 = w * 16;
        #pragma unroll
        for (int kk = 0; kk < 4; kk++) {
            int row = r0 + lr + ((sel & 1) ? 8 : 0);
            int ch  = 2 * kk + (sel >> 1);
            LDM4(QAh[kk][0], QAh[kk][1], QAh[kk][2], QAh[kk][3], sQh + swz(row, ch));
            LDM4(QAl[kk][0], QAl[kk][1], QAl[kk][2], QAl[kk][3], sQl + swz(row, ch));
        }
    }

    float O[8][4] = {};
    float m0 = -1e30f, m1 = -1e30f, l0 = 0.f, l1 = 0.f;

    #pragma unroll 1
    for (int kt = 0; kt < 32; kt++) {
        const uint32_t st  = sb + 32768 + (kt & 1) * 32768;
        const uint32_t sKh = st, sKl = st + 8192;
        const uint32_t sVh = st + 16384, sVl = st + 24576;

        float S[8][4];
        #pragma unroll
        for (int g = 0; g < 8; g++)
            S[g][0] = S[g][1] = S[g][2] = S[g][3] = 0.f;

        #pragma unroll
        for (int kk = 0; kk < 4; kk++) {
            uint32_t bk[4][4];
            #pragma unroll
            for (int jp = 0; jp < 4; jp++) {
                int row = jp * 16 + lr + ((sel & 2) ? 8 : 0);
                int ch  = 2 * kk + (sel & 1);
                LDM4(bk[jp][0], bk[jp][1], bk[jp][2], bk[jp][3], sKh + swz(row, ch));
            }
            #pragma unroll
            for (int jp = 0; jp < 4; jp++) {
                MMAF(S[2*jp],   QAh[kk], bk[jp][0], bk[jp][1]);
                MMAF(S[2*jp+1], QAh[kk], bk[jp][2], bk[jp][3]);
                MMAF(S[2*jp],   QAl[kk], bk[jp][0], bk[jp][1]);
                MMAF(S[2*jp+1], QAl[kk], bk[jp][2], bk[jp][3]);
            }
        }
        #pragma unroll
        for (int kk = 0; kk < 4; kk++) {
            uint32_t bk[4][4];
            #pragma unroll
            for (int jp = 0; jp < 4; jp++) {
                int row = jp * 16 + lr + ((sel & 2) ? 8 : 0);
                int ch  = 2 * kk + (sel & 1);
                LDM4(bk[jp][0], bk[jp][1], bk[jp][2], bk[jp][3], sKl + swz(row, ch));
            }
            #pragma unroll
            for (int jp = 0; jp < 4; jp++) {
                MMAF(S[2*jp],   QAh[kk], bk[jp][0], bk[jp][1]);
                MMAF(S[2*jp+1], QAh[kk], bk[jp][2], bk[jp][3]);
            }
        }

        float mx0 = -1e30f, mx1 = -1e30f;
        #pragma unroll
        for (int g = 0; g < 8; g++) {
            S[g][0] *= 0.125f; S[g][1] *= 0.125f;
            S[g][2] *= 0.125f; S[g][3] *= 0.125f;
            mx0 = fmaxf(mx0, fmaxf(S[g][0], S[g][1]));
            mx1 = fmaxf(mx1, fmaxf(S[g][2], S[g][3]));
        }
        mx0 = fmaxf(mx0, __shfl_xor_sync(0xffffffffu, mx0, 1));
        mx0 = fmaxf(mx0, __shfl_xor_sync(0xffffffffu, mx0, 2));
        mx1 = fmaxf(mx1, __shfl_xor_sync(0xffffffffu, mx1, 1));
        mx1 = fmaxf(mx1, __shfl_xor_sync(0xffffffffu, mx1, 2));
        float mn0 = fmaxf(m0, mx0), mn1 = fmaxf(m1, mx1);
        float c0 = __expf(m0 - mn0), c1 = __expf(m1 - mn1);
        float sum0 = 0.f, sum1 = 0.f;
        #pragma unroll
        for (int g = 0; g < 8; g++) {
            S[g][0] = __expf(S[g][0] - mn0);
            S[g][1] = __expf(S[g][1] - mn0);
            S[g][2] = __expf(S[g][2] - mn1);
            S[g][3] = __expf(S[g][3] - mn1);
            sum0 += S[g][0] + S[g][1];
            sum1 += S[g][2] + S[g][3];
        }
        sum0 += __shfl_xor_sync(0xffffffffu, sum0, 1);
        sum0 += __shfl_xor_sync(0xffffffffu, sum0, 2);
        sum1 += __shfl_xor_sync(0xffffffffu, sum1, 1);
        sum1 += __shfl_xor_sync(0xffffffffu, sum1, 2);
        l0 = l0 * c0 + sum0;  l1 = l1 * c1 + sum1;
        m0 = mn0;  m1 = mn1;
        #pragma unroll
        for (int g = 0; g < 8; g++) {
            O[g][0] *= c0; O[g][1] *= c0;
            O[g][2] *= c1; O[g][3] *= c1;
        }

        #pragma unroll
        for (int kk = 0; kk < 4; kk++) {
            uint32_t pah[4], pal[4];
            {
                float* A0 = S[2*kk];
                float* A1 = S[2*kk+1];
                pah[0] = pack_bf2(A0[0], A0[1]);
                pah[1] = pack_bf2(A0[2], A0[3]);
                pah[2] = pack_bf2(A1[0], A1[1]);
                pah[3] = pack_bf2(A1[2], A1[3]);
                float2 f0 = unpack_bf2(pah[0]), f1 = unpack_bf2(pah[1]);
                float2 f2 = unpack_bf2(pah[2]), f3 = unpack_bf2(pah[3]);
                pal[0] = pack_bf2(A0[0] - f0.x, A0[1] - f0.y);
                pal[1] = pack_bf2(A0[2] - f1.x, A0[3] - f1.y);
                pal[2] = pack_bf2(A1[0] - f2.x, A1[1] - f2.y);
                pal[3] = pack_bf2(A1[2] - f3.x, A1[3] - f3.y);
            }
            uint32_t bv[4][4];
            #pragma unroll
            for (int jp = 0; jp < 4; jp++) {
                int row = kk * 16 + lr + ((sel & 1) ? 8 : 0);
                int ch  = 2 * jp + (sel >> 1);
                LDM4T(bv[jp][0], bv[jp][1], bv[jp][2], bv[jp][3], sVh + swz(row, ch));
            }
            #pragma unroll
            for (int jp = 0; jp < 4; jp++) {
                MMAF(O[2*jp],   pah, bv[jp][0], bv[jp][1]);
                MMAF(O[2*jp+1], pah, bv[jp][2], bv[jp][3]);
                MMAF(O[2*jp],   pal, bv[jp][0], bv[jp][1]);
                MMAF(O[2*jp+1], pal, bv[jp][2], bv[jp][3]);
            }
            #pragma unroll
            for (int jp = 0; jp < 4; jp++) {
                int row = kk * 16 + lr + ((sel & 1) ? 8 : 0);
                int ch  = 2 * jp + (sel >> 1);
                LDM4T(bv[jp][0], bv[jp][1], bv[jp][2], bv[jp][3], sVl + swz(row, ch));
            }
            #pragma unroll
            for (int jp = 0; jp < 4; jp++) {
                MMAF(O[2*jp],   pah, bv[jp][0], bv[jp][1]);
                MMAF(O[2*jp+1], pah, bv[jp][2], bv[jp][3]);
            }
        }

        __syncthreads();
        if (kt + 2 < 32) ISSUE_KV(kt + 2, sb + 32768 + (kt & 1) * 32768);
        if (kt + 1 < 32) {
            if (kt + 2 < 32) CPA_WAIT1(); else CPA_WAIT0();
            __syncthreads();
        }
    }
    #undef ISSUE_KV

    {
        float inv0 = 1.f / l0, inv1 = 1.f / l1;
        int row = b * SQL + qt * 128 + w * 16 + (lane >> 2);
        size_t base = (size_t)row * HID + h * HD + (lane & 3) * 2;
        #pragma unroll
        for (int g = 0; g < 8; g++) {
            float x0 = O[g][0] * inv0, x1 = O[g][1] * inv0;
            float y0 = O[g][2] * inv1, y1 = O[g][3] * inv1;
            __nv_bfloat16 h0 = __float2bfloat16(x0), h1 = __float2bfloat16(x1);
            __nv_bfloat16 g0 = __float2bfloat16(y0), g1 = __float2bfloat16(y1);
            *(__nv_bfloat162*)(xout + base + 8 * g) = __halves2bfloat162(h0, h1);
            *(__nv_bfloat162*)(xout + NQ + base + 8 * g) =
                __halves2bfloat162(__float2bfloat16(x0 - __bfloat162float(h0)),
                                   __float2bfloat16(x1 - __bfloat162float(h1)));
            *(__nv_bfloat162*)(xout + base + 8 * HID + 8 * g) = __halves2bfloat162(g0, g1);
            *(__nv_bfloat162*)(xout + NQ + base + 8 * HID + 8 * g) =
                __halves2bfloat162(__float2bfloat16(y0 - __bfloat162float(g0)),
                                   __float2bfloat16(y1 - __bfloat162float(g1)));
        }
    }
}

// ---------------------------------------------------------------------------
extern "C" void kernel_launch(void* const* d_in, const int* in_sizes, int n_in,
                              void* d_out, int out_size)
{
    const float* xq   = (const float*)d_in[0];
    const float* xkv  = (const float*)d_in[1];
    const float* Wq   = (const float*)d_in[2];
    const float* Wkv  = (const float*)d_in[3];
    const float* Wout = (const float*)d_in[4];
    const float* bout = (const float*)d_in[5];
    float* out = (float*)d_out;

    void *p_xq, *p_xkv, *p_wq, *p_wkv, *p_wo, *p_x, *p_qa, *p_kva;
    cudaGetSymbolAddress(&p_xq,  s_xq);
    cudaGetSymbolAddress(&p_xkv, s_xkv);
    cudaGetSymbolAddress(&p_wq,  s_wq);
    cudaGetSymbolAddress(&p_wkv, s_wkv);
    cudaGetSymbolAddress(&p_wo,  s_wo);
    cudaGetSymbolAddress(&p_x,   s_x);
    cudaGetSymbolAddress(&p_qa,  s_qa);
    cudaGetSymbolAddress(&p_kva, s_kva);

    cudaFuncSetAttribute(attn_mma,
        cudaFuncAttributeMaxDynamicSharedMemorySize, AT_SMEM);
    cudaFuncSetAttribute(gemm_mma2<1>,
        cudaFuncAttributeMaxDynamicSharedMemorySize, GSMEM);
    cudaFuncSetAttribute(gemm_mma2<2>,
        cudaFuncAttributeMaxDynamicSharedMemorySize, GSMEM);

    auto sp = [](const float* X, void* S, int n) {
        split_bf16_k<<<(n / 4 + 255) / 256, 256>>>(X, (__nv_bfloat16*)S, n);
    };
    sp(xq,   p_xq,  NB * SQL * HID);
    sp(xkv,  p_xkv, NB * SKV * HID);
    sp(Wq,   p_wq,  HID * HID);
    sp(Wkv,  p_wkv, 2 * HID * HID);
    sp(Wout, p_wo,  HID * HID);

    // q = xq @ Wq^T  -> split-bf16 directly into s_qa
    gemm_mma2<2><<<dim3(HID / 128, (NB * SQL) / 256), 256, GSMEM>>>(
        (const __nv_bfloat16*)p_xq, (const __nv_bfloat16*)p_wq,
        nullptr, p_qa, NB * SQL, HID);

    // kv = xkv @ Wkv^T  -> split-bf16 directly into s_kva
    gemm_mma2<2><<<dim3((2 * HID) / 128, (NB * SKV) / 256), 256, GSMEM>>>(
        (const __nv_bfloat16*)p_xkv, (const __nv_bfloat16*)p_wkv,
        nullptr, p_kva, NB * SKV, 2 * HID);

    // attention (writes split-bf16 x directly)
    attn_mma<<<dim3(SQL / 128, NB * NH), 256, AT_SMEM>>>(
        (const __nv_bfloat16*)p_qa, (const __nv_bfloat16*)p_kva,
        (__nv_bfloat16*)p_x);

    // out = x @ Wout^T + bout
    gemm_mma2<1><<<dim3(HID / 128, (NB * SQL) / 256), 256, GSMEM>>>(
        (const __nv_bfloat16*)p_x, (const __nv_bfloat16*)p_wo,
        bout, out, NB * SQL, HID);
}

// round 7
// speedup vs baseline: 3.3517x; 1.1760x over previous
#include <cuda_runtime.h>
#include <cuda_bf16.h>
#include <math.h>
#include <stdint.h>

#define HID 1024
#define NH  16
#define HD  64
#define NB  4
#define SQL 1024
#define SKV 2048

// ---------------- scratch (__device__ globals; no allocs allowed) ----------
// split-bf16: hi in first n elements, lo in next n
__device__ __nv_bfloat16 s_xq [(size_t)2 * NB * SQL * HID];
__device__ __nv_bfloat16 s_xkv[(size_t)2 * NB * SKV * HID];
__device__ __nv_bfloat16 s_wq [(size_t)2 * HID * HID];
__device__ __nv_bfloat16 s_wkv[(size_t)2 * 2 * HID * HID];
__device__ __nv_bfloat16 s_wo [(size_t)2 * HID * HID];
__device__ __nv_bfloat16 s_x  [(size_t)2 * NB * SQL * HID];
__device__ __nv_bfloat16 s_qa [(size_t)2 * NB * SQL * HID];       // split q
__device__ __nv_bfloat16 s_kva[(size_t)2 * NB * SKV * 2 * HID];   // split kv

// ---------------------------------------------------------------------------
static __device__ __forceinline__ uint32_t smem_u32(const void* p) {
    uint32_t a;
    asm("{ .reg .u64 t; cvta.to.shared.u64 t, %1; cvt.u32.u64 %0, t; }"
        : "=r"(a) : "l"(p));
    return a;
}

#define CPA16(dst, src) \
    asm volatile("cp.async.cg.shared.global [%0], [%1], 16;" \
                 :: "r"(dst), "l"(src) : "memory")
#define CPA_COMMIT() asm volatile("cp.async.commit_group;" ::: "memory")
#define CPA_WAIT1()  asm volatile("cp.async.wait_group 1;" ::: "memory")
#define CPA_WAIT0()  asm volatile("cp.async.wait_group 0;" ::: "memory")

#define LDM4(r0, r1, r2, r3, addr) \
    asm volatile("ldmatrix.sync.aligned.m8n8.x4.shared.b16 {%0,%1,%2,%3}, [%4];" \
                 : "=r"(r0), "=r"(r1), "=r"(r2), "=r"(r3) : "r"(addr))
#define LDM4T(r0, r1, r2, r3, addr) \
    asm volatile("ldmatrix.sync.aligned.m8n8.x4.trans.shared.b16 {%0,%1,%2,%3}, [%4];" \
                 : "=r"(r0), "=r"(r1), "=r"(r2), "=r"(r3) : "r"(addr))

#define MMAF(d, a, b0, b1) \
    asm volatile("mma.sync.aligned.m16n8k16.row.col.f32.bf16.bf16.f32 " \
                 "{%0,%1,%2,%3}, {%4,%5,%6,%7}, {%8,%9}, {%0,%1,%2,%3};" \
                 : "+f"((d)[0]), "+f"((d)[1]), "+f"((d)[2]), "+f"((d)[3]) \
                 : "r"((a)[0]), "r"((a)[1]), "r"((a)[2]), "r"((a)[3]), \
                   "r"(b0), "r"(b1))

// GEMM smem swizzle: 32-bf16 (64B) rows, 4 chunks of 16B
static __device__ __forceinline__ uint32_t sw(int r, int c) {
    return (uint32_t)(r * 64 + ((c ^ ((r >> 1) & 3)) * 16));
}
// attention smem swizzle: 64-bf16 (128B) rows, 8 chunks
static __device__ __forceinline__ uint32_t swz(int r, int c) {
    return (uint32_t)(r * 128 + ((c ^ (r & 7)) * 16));
}

static __device__ __forceinline__ uint32_t pack_bf2(float lo, float hi) {
    __nv_bfloat162 t = __float22bfloat162_rn(make_float2(lo, hi));
    return *(uint32_t*)&t;
}
static __device__ __forceinline__ float2 unpack_bf2(uint32_t u) {
    __nv_bfloat162 t = *(__nv_bfloat162*)&u;
    return __bfloat1622float2(t);
}

// ---------------------------------------------------------------------------
// split fp32 -> (hi, lo) bf16
// ---------------------------------------------------------------------------
__global__ void split_bf16_k(const float* __restrict__ X,
                             __nv_bfloat16* __restrict__ S, int n)
{
    int i = (blockIdx.x * blockDim.x + threadIdx.x) * 4;
    if (i >= n) return;
    float4 x = *(const float4*)(X + i);
    float v[4] = {x.x, x.y, x.z, x.w};
    __nv_bfloat16 h[4], l[4];
    #pragma unroll
    for (int j = 0; j < 4; j++) {
        h[j] = __float2bfloat16(v[j]);
        l[j] = __float2bfloat16(v[j] - __bfloat162float(h[j]));
    }
    *(__nv_bfloat162*)(S + i)         = __halves2bfloat162(h[0], h[1]);
    *(__nv_bfloat162*)(S + i + 2)     = __halves2bfloat162(h[2], h[3]);
    *(__nv_bfloat162*)(S + n + i)     = __halves2bfloat162(l[0], l[1]);
    *(__nv_bfloat162*)(S + n + i + 2) = __halves2bfloat162(l[2], l[3]);
}

// ---------------------------------------------------------------------------
// Split-bf16 NT GEMM v3 via mma.sync.
// Block 128x128, BK=32, 4 warps (2m x 2n), warp tile 64x64.
// 3-stage cp.async ring, 48KB smem, 2 CTAs/SM.
// OMODE: 1 = fp32 + bias, 2 = split-bf16 out (hi @C, lo @C+M*N).
// ---------------------------------------------------------------------------
#define G3_STAGE 16384                  // A 8KB + B 8KB
#define G3_SMEM  (3 * G3_STAGE)         // 49152

template<int OMODE>
__global__ __launch_bounds__(128, 2) void gemm_mma3(
    const __nv_bfloat16* __restrict__ A, const __nv_bfloat16* __restrict__ B,
    const float* __restrict__ bias, void* __restrict__ Cv, int M, int N)
{
    extern __shared__ __align__(1024) char smem[];
    const uint32_t sb = smem_u32(smem);

    const int tid  = threadIdx.x;
    const int wid  = tid >> 5;
    const int lane = tid & 31;
    const int m0   = blockIdx.y * 128;
    const int n0   = blockIdx.x * 128;
    const int wm   = wid & 1;           // 2 warp rows (64 each)
    const int wn   = wid >> 1;          // 2 warp cols (64 each)

    const size_t MK = (size_t)M * HID, NK = (size_t)N * HID;
    const int NIT = 96;                 // 3 segments x 32 k-blocks

    #define PRE(it, s) do {                                                   \
        int _seg = (it) >> 5, _kb = (it) & 31;                                \
        const __nv_bfloat16* _Ab = A + (_seg == 2 ? MK : 0);                  \
        const __nv_bfloat16* _Bb = B + (_seg == 1 ? NK : 0);                  \
        uint32_t _ba = sb + (s) * G3_STAGE;                                   \
        _Pragma("unroll")                                                     \
        for (int _q = 0; _q < 4; _q++) {                                      \
            int _ch = tid + _q * 128;                                         \
            int _r = _ch >> 2, _c = _ch & 3;                                  \
            CPA16(_ba + sw(_r, _c),                                           \
                  _Ab + (size_t)(m0 + _r) * HID + _kb * 32 + _c * 8);         \
            CPA16(_ba + 8192 + sw(_r, _c),                                    \
                  _Bb + (size_t)(n0 + _r) * HID + _kb * 32 + _c * 8);         \
        }                                                                     \
        CPA_COMMIT();                                                         \
    } while (0)

    float d[4][8][4] = {};

    PRE(0, 0); PRE(1, 1);

    #pragma unroll 1
    for (int it = 0; it < NIT; it++) {
        if (it < NIT - 1) CPA_WAIT1(); else CPA_WAIT0();
        __syncthreads();

        const uint32_t sa  = sb + (it % 3) * G3_STAGE;
        const uint32_t sbm = sa + 8192;

        #pragma unroll
        for (int ks = 0; ks < 2; ks++) {
            uint32_t a[4][4];
            #pragma unroll
            for (int mi = 0; mi < 4; mi++) {
                int r = wm * 64 + mi * 16 + (lane & 15);
                int c = ks * 2 + ((lane >> 4) & 1);
                LDM4(a[mi][0], a[mi][1], a[mi][2], a[mi][3], sa + sw(r, c));
            }
            uint32_t b[8][2];
            #pragma unroll
            for (int ni = 0; ni < 4; ni++) {
                int r = wn * 64 + ni * 16 + ((lane >> 4) & 1) * 8 + (lane & 7);
                int c = ks * 2 + ((lane >> 3) & 1);
                uint32_t r0, r1, r2, r3;
                LDM4(r0, r1, r2, r3, sbm + sw(r, c));
                b[ni * 2][0] = r0;     b[ni * 2][1] = r1;
                b[ni * 2 + 1][0] = r2; b[ni * 2 + 1][1] = r3;
            }
            #pragma unroll
            for (int mi = 0; mi < 4; mi++)
                #pragma unroll
                for (int nj = 0; nj < 8; nj++)
                    MMAF(d[mi][nj], a[mi], b[nj][0], b[nj][1]);
        }
        if (it + 2 < NIT) PRE(it + 2, (it + 2) % 3);
    }
    #undef PRE

    // ---- epilogue ----
    const int row0 = m0 + wm * 64 + (lane >> 2);
    const int col0 = n0 + wn * 64 + (lane & 3) * 2;

    if (OMODE == 1) {
        float* C = (float*)Cv;
        #pragma unroll
        for (int mi = 0; mi < 4; mi++) {
            #pragma unroll
            for (int nj = 0; nj < 8; nj++) {
                int r = row0 + mi * 16;
                int cc = col0 + nj * 8;
                float b0 = __ldg(bias + cc), b1 = __ldg(bias + cc + 1);
                *(float2*)(C + (size_t)r * N + cc) =
                    make_float2(d[mi][nj][0] + b0, d[mi][nj][1] + b1);
                *(float2*)(C + (size_t)(r + 8) * N + cc) =
                    make_float2(d[mi][nj][2] + b0, d[mi][nj][3] + b1);
            }
        }
    } else {
        __nv_bfloat16* C = (__nv_bfloat16*)Cv;
        const size_t MN = (size_t)M * N;
        #pragma unroll
        for (int mi = 0; mi < 4; mi++) {
            #pragma unroll
            for (int nj = 0; nj < 8; nj++) {
                int r = row0 + mi * 16;
                int cc = col0 + nj * 8;
                #pragma unroll
                for (int half = 0; half < 2; half++) {
                    float v0 = d[mi][nj][half * 2];
                    float v1 = d[mi][nj][half * 2 + 1];
                    size_t off = (size_t)(r + half * 8) * N + cc;
                    __nv_bfloat16 h0 = __float2bfloat16(v0);
                    __nv_bfloat16 h1 = __float2bfloat16(v1);
                    *(__nv_bfloat162*)(C + off) = __halves2bfloat162(h0, h1);
                    *(__nv_bfloat162*)(C + MN + off) = __halves2bfloat162(
                        __float2bfloat16(v0 - __bfloat162float(h0)),
                        __float2bfloat16(v1 - __bfloat162float(h1)));
                }
            }
        }
    }
}

// ---------------------------------------------------------------------------
// Split-bf16 mma.sync flash attention (unchanged from R5).
// ---------------------------------------------------------------------------
#define AT_SMEM 98304

__global__ __launch_bounds__(256, 1) void attn_mma(
    const __nv_bfloat16* __restrict__ q,
    const __nv_bfloat16* __restrict__ kvs,
    __nv_bfloat16* __restrict__ xout)
{
    extern __shared__ __align__(1024) char smem[];
    const uint32_t sb  = smem_u32(smem);
    const uint32_t sQh = sb, sQl = sb + 16384;

    const int tid  = threadIdx.x;
    const int lane = tid & 31;
    const int w    = tid >> 5;
    const int lr   = lane & 7;
    const int sel  = lane >> 3;

    const int qt = blockIdx.x;
    const int bh = blockIdx.y;
    const int b  = bh >> 4;
    const int h  = bh & 15;

    const size_t NQ  = (size_t)NB * SQL * HID;
    const size_t NKV = (size_t)NB * SKV * 2 * HID;

    const __nv_bfloat16* Qb = q   + (size_t)(b * SQL + qt * 128) * HID + h * HD;
    const __nv_bfloat16* Kb = kvs + (size_t)b * SKV * 2 * HID + h * HD;

    {
        #pragma unroll
        for (int qq = 0; qq < 4; qq++) {
            int ch = tid * 4 + qq;
            int r = ch >> 3, c = ch & 7;
            const __nv_bfloat16* src = Qb + (size_t)r * HID + c * 8;
            CPA16(sQh + swz(r, c), src);
            CPA16(sQl + swz(r, c), src + NQ);
        }
    }
    #define ISSUE_KV(t, st) do {                                              \
        int _kv0 = (t) * 64;                                                  \
        _Pragma("unroll")                                                     \
        for (int _qq = 0; _qq < 2; _qq++) {                                   \
            int _ch = tid * 2 + _qq;                                          \
            int _r = _ch >> 3, _c = _ch & 7;                                  \
            const __nv_bfloat16* _k = Kb + (size_t)(_kv0 + _r) * 2048 + _c * 8; \
            uint32_t _d = swz(_r, _c);                                        \
            CPA16((st) +         _d, _k);                                     \
            CPA16((st) + 8192  + _d, _k + NKV);                               \
            CPA16((st) + 16384 + _d, _k + HID);                               \
            CPA16((st) + 24576 + _d, _k + HID + NKV);                         \
        }                                                                     \
        CPA_COMMIT();                                                         \
    } while (0)

    CPA_COMMIT();
    ISSUE_KV(0, sb + 32768);
    ISSUE_KV(1, sb + 65536);
    CPA_WAIT1();
    __syncthreads();

    uint32_t QAh[4][4], QAl[4][4];
    {
        const int r0 = w * 16;
        #pragma unroll
        for (int kk = 0; kk < 4; kk++) {
            int row = r0 + lr + ((sel & 1) ? 8 : 0);
            int ch  = 2 * kk + (sel >> 1);
            LDM4(QAh[kk][0], QAh[kk][1], QAh[kk][2], QAh[kk][3], sQh + swz(row, ch));
            LDM4(QAl[kk][0], QAl[kk][1], QAl[kk][2], QAl[kk][3], sQl + swz(row, ch));
        }
    }

    float O[8][4] = {};
    float m0 = -1e30f, m1 = -1e30f, l0 = 0.f, l1 = 0.f;

    #pragma unroll 1
    for (int kt = 0; kt < 32; kt++) {
        const uint32_t st  = sb + 32768 + (kt & 1) * 32768;
        const uint32_t sKh = st, sKl = st + 8192;
        const uint32_t sVh = st + 16384, sVl = st + 24576;

        float S[8][4];
        #pragma unroll
        for (int g = 0; g < 8; g++)
            S[g][0] = S[g][1] = S[g][2] = S[g][3] = 0.f;

        #pragma unroll
        for (int kk = 0; kk < 4; kk++) {
            uint32_t bk[4][4];
            #pragma unroll
            for (int jp = 0; jp < 4; jp++) {
                int row = jp * 16 + lr + ((sel & 2) ? 8 : 0);
                int ch  = 2 * kk + (sel & 1);
                LDM4(bk[jp][0], bk[jp][1], bk[jp][2], bk[jp][3], sKh + swz(row, ch));
            }
            #pragma unroll
            for (int jp = 0; jp < 4; jp++) {
                MMAF(S[2*jp],   QAh[kk], bk[jp][0], bk[jp][1]);
                MMAF(S[2*jp+1], QAh[kk], bk[jp][2], bk[jp][3]);
                MMAF(S[2*jp],   QAl[kk], bk[jp][0], bk[jp][1]);
                MMAF(S[2*jp+1], QAl[kk], bk[jp][2], bk[jp][3]);
            }
        }
        #pragma unroll
        for (int kk = 0; kk < 4; kk++) {
            uint32_t bk[4][4];
            #pragma unroll
            for (int jp = 0; jp < 4; jp++) {
                int row = jp * 16 + lr + ((sel & 2) ? 8 : 0);
                int ch  = 2 * kk + (sel & 1);
                LDM4(bk[jp][0], bk[jp][1], bk[jp][2], bk[jp][3], sKl + swz(row, ch));
            }
            #pragma unroll
            for (int jp = 0; jp < 4; jp++) {
                MMAF(S[2*jp],   QAh[kk], bk[jp][0], bk[jp][1]);
                MMAF(S[2*jp+1], QAh[kk], bk[jp][2], bk[jp][3]);
            }
        }

        float mx0 = -1e30f, mx1 = -1e30f;
        #pragma unroll
        for (int g = 0; g < 8; g++) {
            S[g][0] *= 0.125f; S[g][1] *= 0.125f;
            S[g][2] *= 0.125f; S[g][3] *= 0.125f;
            mx0 = fmaxf(mx0, fmaxf(S[g][0], S[g][1]));
            mx1 = fmaxf(mx1, fmaxf(S[g][2], S[g][3]));
        }
        mx0 = fmaxf(mx0, __shfl_xor_sync(0xffffffffu, mx0, 1));
        mx0 = fmaxf(mx0, __shfl_xor_sync(0xffffffffu, mx0, 2));
        mx1 = fmaxf(mx1, __shfl_xor_sync(0xffffffffu, mx1, 1));
        mx1 = fmaxf(mx1, __shfl_xor_sync(0xffffffffu, mx1, 2));
        float mn0 = fmaxf(m0, mx0), mn1 = fmaxf(m1, mx1);
        float c0 = __expf(m0 - mn0), c1 = __expf(m1 - mn1);
        float sum0 = 0.f, sum1 = 0.f;
        #pragma unroll
        for (int g = 0; g < 8; g++) {
            S[g][0] = __expf(S[g][0] - mn0);
            S[g][1] = __expf(S[g][1] - mn0);
            S[g][2] = __expf(S[g][2] - mn1);
            S[g][3] = __expf(S[g][3] - mn1);
            sum0 += S[g][0] + S[g][1];
            sum1 += S[g][2] + S[g][3];
        }
        sum0 += __shfl_xor_sync(0xffffffffu, sum0, 1);
        sum0 += __shfl_xor_sync(0xffffffffu, sum0, 2);
        sum1 += __shfl_xor_sync(0xffffffffu, sum1, 1);
        sum1 += __shfl_xor_sync(0xffffffffu, sum1, 2);
        l0 = l0 * c0 + sum0;  l1 = l1 * c1 + sum1;
        m0 = mn0;  m1 = mn1;
        #pragma unroll
        for (int g = 0; g < 8; g++) {
            O[g][0] *= c0; O[g][1] *= c0;
            O[g][2] *= c1; O[g][3] *= c1;
        }

        #pragma unroll
        for (int kk = 0; kk < 4; kk++) {
            uint32_t pah[4], pal[4];
            {
                float* A0 = S[2*kk];
                float* A1 = S[2*kk+1];
                pah[0] = pack_bf2(A0[0], A0[1]);
                pah[1] = pack_bf2(A0[2], A0[3]);
                pah[2] = pack_bf2(A1[0], A1[1]);
                pah[3] = pack_bf2(A1[2], A1[3]);
                float2 f0 = unpack_bf2(pah[0]), f1 = unpack_bf2(pah[1]);
                float2 f2 = unpack_bf2(pah[2]), f3 = unpack_bf2(pah[3]);
                pal[0] = pack_bf2(A0[0] - f0.x, A0[1] - f0.y);
                pal[1] = pack_bf2(A0[2] - f1.x, A0[3] - f1.y);
                pal[2] = pack_bf2(A1[0] - f2.x, A1[1] - f2.y);
                pal[3] = pack_bf2(A1[2] - f3.x, A1[3] - f3.y);
            }
            uint32_t bv[4][4];
            #pragma unroll
            for (int jp = 0; jp < 4; jp++) {
                int row = kk * 16 + lr + ((sel & 1) ? 8 : 0);
                int ch  = 2 * jp + (sel >> 1);
                LDM4T(bv[jp][0], bv[jp][1], bv[jp][2], bv[jp][3], sVh + swz(row, ch));
            }
            #pragma unroll
            for (int jp = 0; jp < 4; jp++) {
                MMAF(O[2*jp],   pah, bv[jp][0], bv[jp][1]);
                MMAF(O[2*jp+1], pah, bv[jp][2], bv[jp][3]);
                MMAF(O[2*jp],   pal, bv[jp][0], bv[jp][1]);
                MMAF(O[2*jp+1], pal, bv[jp][2], bv[jp][3]);
            }
            #pragma unroll
            for (int jp = 0; jp < 4; jp++) {
                int row = kk * 16 + lr + ((sel & 1) ? 8 : 0);
                int ch  = 2 * jp + (sel >> 1);
                LDM4T(bv[jp][0], bv[jp][1], bv[jp][2], bv[jp][3], sVl + swz(row, ch));
            }
            #pragma unroll
            for (int jp = 0; jp < 4; jp++) {
                MMAF(O[2*jp],   pah, bv[jp][0], bv[jp][1]);
                MMAF(O[2*jp+1], pah, bv[jp][2], bv[jp][3]);
            }
        }

        __syncthreads();
        if (kt + 2 < 32) ISSUE_KV(kt + 2, sb + 32768 + (kt & 1) * 32768);
        if (kt + 1 < 32) {
            if (kt + 2 < 32) CPA_WAIT1(); else CPA_WAIT0();
            __syncthreads();
        }
    }
    #undef ISSUE_KV

    {
        float inv0 = 1.f / l0, inv1 = 1.f / l1;
        int row = b * SQL + qt * 128 + w * 16 + (lane >> 2);
        size_t base = (size_t)row * HID + h * HD + (lane & 3) * 2;
        #pragma unroll
        for (int g = 0; g < 8; g++) {
            float x0 = O[g][0] * inv0, x1 = O[g][1] * inv0;
            float y0 = O[g][2] * inv1, y1 = O[g][3] * inv1;
            __nv_bfloat16 h0 = __float2bfloat16(x0), h1 = __float2bfloat16(x1);
            __nv_bfloat16 g0 = __float2bfloat16(y0), g1 = __float2bfloat16(y1);
            *(__nv_bfloat162*)(xout + base + 8 * g) = __halves2bfloat162(h0, h1);
            *(__nv_bfloat162*)(xout + NQ + base + 8 * g) =
                __halves2bfloat162(__float2bfloat16(x0 - __bfloat162float(h0)),
                                   __float2bfloat16(x1 - __bfloat162float(h1)));
            *(__nv_bfloat162*)(xout + base + 8 * HID + 8 * g) = __halves2bfloat162(g0, g1);
            *(__nv_bfloat162*)(xout + NQ + base + 8 * HID + 8 * g) =
                __halves2bfloat162(__float2bfloat16(y0 - __bfloat162float(g0)),
                                   __float2bfloat16(y1 - __bfloat162float(g1)));
        }
    }
}

// ---------------------------------------------------------------------------
extern "C" void kernel_launch(void* const* d_in, const int* in_sizes, int n_in,
                              void* d_out, int out_size)
{
    const float* xq   = (const float*)d_in[0];
    const float* xkv  = (const float*)d_in[1];
    const float* Wq   = (const float*)d_in[2];
    const float* Wkv  = (const float*)d_in[3];
    const float* Wout = (const float*)d_in[4];
    const float* bout = (const float*)d_in[5];
    float* out = (float*)d_out;

    void *p_xq, *p_xkv, *p_wq, *p_wkv, *p_wo, *p_x, *p_qa, *p_kva;
    cudaGetSymbolAddress(&p_xq,  s_xq);
    cudaGetSymbolAddress(&p_xkv, s_xkv);
    cudaGetSymbolAddress(&p_wq,  s_wq);
    cudaGetSymbolAddress(&p_wkv, s_wkv);
    cudaGetSymbolAddress(&p_wo,  s_wo);
    cudaGetSymbolAddress(&p_x,   s_x);
    cudaGetSymbolAddress(&p_qa,  s_qa);
    cudaGetSymbolAddress(&p_kva, s_kva);

    cudaFuncSetAttribute(attn_mma,
        cudaFuncAttributeMaxDynamicSharedMemorySize, AT_SMEM);
    cudaFuncSetAttribute(gemm_mma3<1>,
        cudaFuncAttributeMaxDynamicSharedMemorySize, G3_SMEM);
    cudaFuncSetAttribute(gemm_mma3<2>,
        cudaFuncAttributeMaxDynamicSharedMemorySize, G3_SMEM);

    auto sp = [](const float* X, void* S, int n) {
        split_bf16_k<<<(n / 4 + 255) / 256, 256>>>(X, (__nv_bfloat16*)S, n);
    };
    sp(xq,   p_xq,  NB * SQL * HID);
    sp(xkv,  p_xkv, NB * SKV * HID);
    sp(Wq,   p_wq,  HID * HID);
    sp(Wkv,  p_wkv, 2 * HID * HID);
    sp(Wout, p_wo,  HID * HID);

    // q = xq @ Wq^T  -> split-bf16 directly into s_qa
    gemm_mma3<2><<<dim3(HID / 128, (NB * SQL) / 128), 128, G3_SMEM>>>(
        (const __nv_bfloat16*)p_xq, (const __nv_bfloat16*)p_wq,
        nullptr, p_qa, NB * SQL, HID);

    // kv = xkv @ Wkv^T  -> split-bf16 directly into s_kva
    gemm_mma3<2><<<dim3((2 * HID) / 128, (NB * SKV) / 128), 128, G3_SMEM>>>(
        (const __nv_bfloat16*)p_xkv, (const __nv_bfloat16*)p_wkv,
        nullptr, p_kva, NB * SKV, 2 * HID);

    // attention (writes split-bf16 x directly)
    attn_mma<<<dim3(SQL / 128, NB * NH), 256, AT_SMEM>>>(
        (const __nv_bfloat16*)p_qa, (const __nv_bfloat16*)p_kva,
        (__nv_bfloat16*)p_x);

    // out = x @ Wout^T + bout
    gemm_mma3<1><<<dim3(HID / 128, (NB * SQL) / 128), 128, G3_SMEM>>>(
        (const __nv_bfloat16*)p_x, (const __nv_bfloat16*)p_wo,
        bout, out, NB * SQL, HID);
}

// round 8
// speedup vs baseline: 3.6184x; 1.0796x over previous
#include <cuda_runtime.h>
#include <cuda_bf16.h>
#include <math.h>
#include <stdint.h>

#define HID 1024
#define NH  16
#define HD  64
#define NB  4
#define SQL 1024
#define SKV 2048

// ---------------- scratch (__device__ globals; no allocs allowed) ----------
// split-bf16: hi in first n elements, lo in next n
__device__ __nv_bfloat16 s_xq [(size_t)2 * NB * SQL * HID];
__device__ __nv_bfloat16 s_xkv[(size_t)2 * NB * SKV * HID];
__device__ __nv_bfloat16 s_wq [(size_t)2 * HID * HID];
__device__ __nv_bfloat16 s_wkv[(size_t)2 * 2 * HID * HID];
__device__ __nv_bfloat16 s_wo [(size_t)2 * HID * HID];
__device__ __nv_bfloat16 s_x  [(size_t)2 * NB * SQL * HID];
__device__ __nv_bfloat16 s_qa [(size_t)2 * NB * SQL * HID];       // split q
__device__ __nv_bfloat16 s_kva[(size_t)2 * NB * SKV * 2 * HID];   // split kv

// ---------------------------------------------------------------------------
static __device__ __forceinline__ uint32_t smem_u32(const void* p) {
    uint32_t a;
    asm("{ .reg .u64 t; cvta.to.shared.u64 t, %1; cvt.u32.u64 %0, t; }"
        : "=r"(a) : "l"(p));
    return a;
}

#define CPA16(dst, src) \
    asm volatile("cp.async.cg.shared.global [%0], [%1], 16;" \
                 :: "r"(dst), "l"(src) : "memory")
#define CPA_COMMIT() asm volatile("cp.async.commit_group;" ::: "memory")
#define CPA_WAIT1()  asm volatile("cp.async.wait_group 1;" ::: "memory")
#define CPA_WAIT0()  asm volatile("cp.async.wait_group 0;" ::: "memory")

#define LDM4(r0, r1, r2, r3, addr) \
    asm volatile("ldmatrix.sync.aligned.m8n8.x4.shared.b16 {%0,%1,%2,%3}, [%4];" \
                 : "=r"(r0), "=r"(r1), "=r"(r2), "=r"(r3) : "r"(addr))
#define LDM4T(r0, r1, r2, r3, addr) \
    asm volatile("ldmatrix.sync.aligned.m8n8.x4.trans.shared.b16 {%0,%1,%2,%3}, [%4];" \
                 : "=r"(r0), "=r"(r1), "=r"(r2), "=r"(r3) : "r"(addr))

#define MMAF(d, a, b0, b1) \
    asm volatile("mma.sync.aligned.m16n8k16.row.col.f32.bf16.bf16.f32 " \
                 "{%0,%1,%2,%3}, {%4,%5,%6,%7}, {%8,%9}, {%0,%1,%2,%3};" \
                 : "+f"((d)[0]), "+f"((d)[1]), "+f"((d)[2]), "+f"((d)[3]) \
                 : "r"((a)[0]), "r"((a)[1]), "r"((a)[2]), "r"((a)[3]), \
                   "r"(b0), "r"(b1))

// GEMM smem swizzle: 32-bf16 (64B) rows, 4 chunks of 16B
static __device__ __forceinline__ uint32_t sw(int r, int c) {
    return (uint32_t)(r * 64 + ((c ^ ((r >> 1) & 3)) * 16));
}
// attention smem swizzle: 64-bf16 (128B) rows, 8 chunks
static __device__ __forceinline__ uint32_t swz(int r, int c) {
    return (uint32_t)(r * 128 + ((c ^ (r & 7)) * 16));
}

static __device__ __forceinline__ uint32_t pack_bf2(float lo, float hi) {
    __nv_bfloat162 t = __float22bfloat162_rn(make_float2(lo, hi));
    return *(uint32_t*)&t;
}
static __device__ __forceinline__ float2 unpack_bf2(uint32_t u) {
    __nv_bfloat162 t = *(__nv_bfloat162*)&u;
    return __bfloat1622float2(t);
}

// ---------------------------------------------------------------------------
// split fp32 -> (hi, lo) bf16
// ---------------------------------------------------------------------------
__global__ void split_bf16_k(const float* __restrict__ X,
                             __nv_bfloat16* __restrict__ S, int n)
{
    int i = (blockIdx.x * blockDim.x + threadIdx.x) * 4;
    if (i >= n) return;
    float4 x = *(const float4*)(X + i);
    float v[4] = {x.x, x.y, x.z, x.w};
    __nv_bfloat16 h[4], l[4];
    #pragma unroll
    for (int j = 0; j < 4; j++) {
        h[j] = __float2bfloat16(v[j]);
        l[j] = __float2bfloat16(v[j] - __bfloat162float(h[j]));
    }
    *(__nv_bfloat162*)(S + i)         = __halves2bfloat162(h[0], h[1]);
    *(__nv_bfloat162*)(S + i + 2)     = __halves2bfloat162(h[2], h[3]);
    *(__nv_bfloat162*)(S + n + i)     = __halves2bfloat162(l[0], l[1]);
    *(__nv_bfloat162*)(S + n + i + 2) = __halves2bfloat162(l[2], l[3]);
}

// ---------------------------------------------------------------------------
// Split-bf16 NT GEMM v4: single-load-per-element staging.
// Block 128x128, 4 warps (2m x 2n), warp tile 64x64, BK=32.
// 3-slot ring of 16KB pair-stages: A-pair = [Ah(8K)|Al(8K)], B-pair likewise.
// Per k-block: d += Ah*Bh + Al*Bh + Ah*Bl  (one accumulator set).
// Traffic: 4B per fp32 element per k-block (was 6B).
// OMODE: 1 = fp32 + bias, 2 = split-bf16 out (hi @C, lo @C+M*N).
// ---------------------------------------------------------------------------
#define G4_SLOT 16384
#define G4_SMEM (3 * G4_SLOT)           // 49152 -> 2 CTAs/SM

template<int OMODE>
__global__ __launch_bounds__(128, 2) void gemm_mma4(
    const __nv_bfloat16* __restrict__ A, const __nv_bfloat16* __restrict__ B,
    const float* __restrict__ bias, void* __restrict__ Cv, int M, int N)
{
    extern __shared__ __align__(1024) char smem[];
    const uint32_t sb = smem_u32(smem);

    const int tid  = threadIdx.x;
    const int wid  = tid >> 5;
    const int lane = tid & 31;
    const int m0   = blockIdx.y * 128;
    const int n0   = blockIdx.x * 128;
    const int wm   = wid & 1;           // 2 warp rows (64 each)
    const int wn   = wid >> 1;          // 2 warp cols (64 each)

    const size_t MK = (size_t)M * HID, NK = (size_t)N * HID;
    const int NKB = 32;                 // 1024 / BK32

    // load hi+lo pair for one k-block into slot s (hi at +0, lo at +8192)
    #define PRE_A(kb, s) do {                                                 \
        uint32_t _ba = sb + (s) * G4_SLOT;                                    \
        _Pragma("unroll")                                                     \
        for (int _q = 0; _q < 4; _q++) {                                      \
            int _ch = tid + _q * 128;                                         \
            int _r = _ch >> 2, _c = _ch & 3;                                  \
            const __nv_bfloat16* _p = A + (size_t)(m0 + _r) * HID + (kb) * 32 + _c * 8; \
            CPA16(_ba + sw(_r, _c), _p);                                      \
            CPA16(_ba + 8192 + sw(_r, _c), _p + MK);                          \
        }                                                                     \
        CPA_COMMIT();                                                         \
    } while (0)
    #define PRE_B(kb, s) do {                                                 \
        uint32_t _ba = sb + (s) * G4_SLOT;                                    \
        _Pragma("unroll")                                                     \
        for (int _q = 0; _q < 4; _q++) {                                      \
            int _ch = tid + _q * 128;                                         \
            int _r = _ch >> 2, _c = _ch & 3;                                  \
            const __nv_bfloat16* _p = B + (size_t)(n0 + _r) * HID + (kb) * 32 + _c * 8; \
            CPA16(_ba + sw(_r, _c), _p);                                      \
            CPA16(_ba + 8192 + sw(_r, _c), _p + NK);                          \
        }                                                                     \
        CPA_COMMIT();                                                         \
    } while (0)

    float d[4][8][4] = {};

    PRE_A(0, 0); PRE_B(0, 1); PRE_A(1, 2);
    int sa_ = 0, sb_ = 1, sf_ = 2;

    #pragma unroll 1
    for (int kb = 0; kb < NKB; kb++) {
        if (kb < NKB - 1) CPA_WAIT1(); else CPA_WAIT0();
        __syncthreads();

        const uint32_t ah_base = sb + sa_ * G4_SLOT;
        const uint32_t al_base = ah_base + 8192;
        const uint32_t bh_base = sb + sb_ * G4_SLOT;
        const uint32_t bl_base = bh_base + 8192;

        #pragma unroll
        for (int ks = 0; ks < 2; ks++) {
            // fragment coordinates
            const int ar = wm * 64 + (lane & 15);
            const int ac = ks * 2 + ((lane >> 4) & 1);
            const int br = wn * 64 + ((lane >> 4) & 1) * 8 + (lane & 7);
            const int bc = ks * 2 + ((lane >> 3) & 1);

            uint32_t ah[4][4], bh[8][2];
            #pragma unroll
            for (int mi = 0; mi < 4; mi++)
                LDM4(ah[mi][0], ah[mi][1], ah[mi][2], ah[mi][3],
                     ah_base + sw(ar + mi * 16, ac));
            #pragma unroll
            for (int ni = 0; ni < 4; ni++) {
                uint32_t r0, r1, r2, r3;
                LDM4(r0, r1, r2, r3, bh_base + sw(br + ni * 16, bc));
                bh[ni * 2][0] = r0;     bh[ni * 2][1] = r1;
                bh[ni * 2 + 1][0] = r2; bh[ni * 2 + 1][1] = r3;
            }
            // P1: Ah * Bh
            #pragma unroll
            for (int mi = 0; mi < 4; mi++)
                #pragma unroll
                for (int nj = 0; nj < 8; nj++)
                    MMAF(d[mi][nj], ah[mi], bh[nj][0], bh[nj][1]);

            // P3: Al * Bh
            {
                uint32_t al[4][4];
                #pragma unroll
                for (int mi = 0; mi < 4; mi++)
                    LDM4(al[mi][0], al[mi][1], al[mi][2], al[mi][3],
                         al_base + sw(ar + mi * 16, ac));
                #pragma unroll
                for (int mi = 0; mi < 4; mi++)
                    #pragma unroll
                    for (int nj = 0; nj < 8; nj++)
                        MMAF(d[mi][nj], al[mi], bh[nj][0], bh[nj][1]);
            }
            // P2: Ah * Bl
            {
                uint32_t bl[8][2];
                #pragma unroll
                for (int ni = 0; ni < 4; ni++) {
                    uint32_t r0, r1, r2, r3;
                    LDM4(r0, r1, r2, r3, bl_base + sw(br + ni * 16, bc));
                    bl[ni * 2][0] = r0;     bl[ni * 2][1] = r1;
                    bl[ni * 2 + 1][0] = r2; bl[ni * 2 + 1][1] = r3;
                }
                #pragma unroll
                for (int mi = 0; mi < 4; mi++)
                    #pragma unroll
                    for (int nj = 0; nj < 8; nj++)
                        MMAF(d[mi][nj], ah[mi], bl[nj][0], bl[nj][1]);
            }
        }
        __syncthreads();

        if (kb + 1 < NKB) PRE_B(kb + 1, sa_);   // into old A slot (just drained)
        if (kb + 2 < NKB) PRE_A(kb + 2, sb_);   // into old B slot
        int na = sf_; sf_ = sb_; sb_ = sa_; sa_ = na;
    }
    #undef PRE_A
    #undef PRE_B

    // ---- epilogue ----
    const int row0 = m0 + wm * 64 + (lane >> 2);
    const int col0 = n0 + wn * 64 + (lane & 3) * 2;

    if (OMODE == 1) {
        float* C = (float*)Cv;
        #pragma unroll
        for (int mi = 0; mi < 4; mi++) {
            #pragma unroll
            for (int nj = 0; nj < 8; nj++) {
                int r = row0 + mi * 16;
                int cc = col0 + nj * 8;
                float b0 = __ldg(bias + cc), b1 = __ldg(bias + cc + 1);
                *(float2*)(C + (size_t)r * N + cc) =
                    make_float2(d[mi][nj][0] + b0, d[mi][nj][1] + b1);
                *(float2*)(C + (size_t)(r + 8) * N + cc) =
                    make_float2(d[mi][nj][2] + b0, d[mi][nj][3] + b1);
            }
        }
    } else {
        __nv_bfloat16* C = (__nv_bfloat16*)Cv;
        const size_t MN = (size_t)M * N;
        #pragma unroll
        for (int mi = 0; mi < 4; mi++) {
            #pragma unroll
            for (int nj = 0; nj < 8; nj++) {
                int r = row0 + mi * 16;
                int cc = col0 + nj * 8;
                #pragma unroll
                for (int half = 0; half < 2; half++) {
                    float v0 = d[mi][nj][half * 2];
                    float v1 = d[mi][nj][half * 2 + 1];
                    size_t off = (size_t)(r + half * 8) * N + cc;
                    __nv_bfloat16 h0 = __float2bfloat16(v0);
                    __nv_bfloat16 h1 = __float2bfloat16(v1);
                    *(__nv_bfloat162*)(C + off) = __halves2bfloat162(h0, h1);
                    *(__nv_bfloat162*)(C + MN + off) = __halves2bfloat162(
                        __float2bfloat16(v0 - __bfloat162float(h0)),
                        __float2bfloat16(v1 - __bfloat162float(h1)));
                }
            }
        }
    }
}

// ---------------------------------------------------------------------------
// Split-bf16 mma.sync flash attention (unchanged from R5).
// ---------------------------------------------------------------------------
#define AT_SMEM 98304

__global__ __launch_bounds__(256, 1) void attn_mma(
    const __nv_bfloat16* __restrict__ q,
    const __nv_bfloat16* __restrict__ kvs,
    __nv_bfloat16* __restrict__ xout)
{
    extern __shared__ __align__(1024) char smem[];
    const uint32_t sb  = smem_u32(smem);
    const uint32_t sQh = sb, sQl = sb + 16384;

    const int tid  = threadIdx.x;
    const int lane = tid & 31;
    const int w    = tid >> 5;
    const int lr   = lane & 7;
    const int sel  = lane >> 3;

    const int qt = blockIdx.x;
    const int bh = blockIdx.y;
    const int b  = bh >> 4;
    const int h  = bh & 15;

    const size_t NQ  = (size_t)NB * SQL * HID;
    const size_t NKV = (size_t)NB * SKV * 2 * HID;

    const __nv_bfloat16* Qb = q   + (size_t)(b * SQL + qt * 128) * HID + h * HD;
    const __nv_bfloat16* Kb = kvs + (size_t)b * SKV * 2 * HID + h * HD;

    {
        #pragma unroll
        for (int qq = 0; qq < 4; qq++) {
            int ch = tid * 4 + qq;
            int r = ch >> 3, c = ch & 7;
            const __nv_bfloat16* src = Qb + (size_t)r * HID + c * 8;
            CPA16(sQh + swz(r, c), src);
            CPA16(sQl + swz(r, c), src + NQ);
        }
    }
    #define ISSUE_KV(t, st) do {                                              \
        int _kv0 = (t) * 64;                                                  \
        _Pragma("unroll")                                                     \
        for (int _qq = 0; _qq < 2; _qq++) {                                   \
            int _ch = tid * 2 + _qq;                                          \
            int _r = _ch >> 3, _c = _ch & 7;                                  \
            const __nv_bfloat16* _k = Kb + (size_t)(_kv0 + _r) * 2048 + _c * 8; \
            uint32_t _d = swz(_r, _c);                                        \
            CPA16((st) +         _d, _k);                                     \
            CPA16((st) + 8192  + _d, _k + NKV);                               \
            CPA16((st) + 16384 + _d, _k + HID);                               \
            CPA16((st) + 24576 + _d, _k + HID + NKV);                         \
        }                                                                     \
        CPA_COMMIT();                                                         \
    } while (0)

    CPA_COMMIT();
    ISSUE_KV(0, sb + 32768);
    ISSUE_KV(1, sb + 65536);
    CPA_WAIT1();
    __syncthreads();

    uint32_t QAh[4][4], QAl[4][4];
    {
        const int r0 = w * 16;
        #pragma unroll
        for (int kk = 0; kk < 4; kk++) {
            int row = r0 + lr + ((sel & 1) ? 8 : 0);
            int ch  = 2 * kk + (sel >> 1);
            LDM4(QAh[kk][0], QAh[kk][1], QAh[kk][2], QAh[kk][3], sQh + swz(row, ch));
            LDM4(QAl[kk][0], QAl[kk][1], QAl[kk][2], QAl[kk][3], sQl + swz(row, ch));
        }
    }

    float O[8][4] = {};
    float m0 = -1e30f, m1 = -1e30f, l0 = 0.f, l1 = 0.f;

    #pragma unroll 1
    for (int kt = 0; kt < 32; kt++) {
        const uint32_t st  = sb + 32768 + (kt & 1) * 32768;
        const uint32_t sKh = st, sKl = st + 8192;
        const uint32_t sVh = st + 16384, sVl = st + 24576;

        float S[8][4];
        #pragma unroll
        for (int g = 0; g < 8; g++)
            S[g][0] = S[g][1] = S[g][2] = S[g][3] = 0.f;

        #pragma unroll
        for (int kk = 0; kk < 4; kk++) {
            uint32_t bk[4][4];
            #pragma unroll
            for (int jp = 0; jp < 4; jp++) {
                int row = jp * 16 + lr + ((sel & 2) ? 8 : 0);
                int ch  = 2 * kk + (sel & 1);
                LDM4(bk[jp][0], bk[jp][1], bk[jp][2], bk[jp][3], sKh + swz(row, ch));
            }
            #pragma unroll
            for (int jp = 0; jp < 4; jp++) {
                MMAF(S[2*jp],   QAh[kk], bk[jp][0], bk[jp][1]);
                MMAF(S[2*jp+1], QAh[kk], bk[jp][2], bk[jp][3]);
                MMAF(S[2*jp],   QAl[kk], bk[jp][0], bk[jp][1]);
                MMAF(S[2*jp+1], QAl[kk], bk[jp][2], bk[jp][3]);
            }
        }
        #pragma unroll
        for (int kk = 0; kk < 4; kk++) {
            uint32_t bk[4][4];
            #pragma unroll
            for (int jp = 0; jp < 4; jp++) {
                int row = jp * 16 + lr + ((sel & 2) ? 8 : 0);
                int ch  = 2 * kk + (sel & 1);
                LDM4(bk[jp][0], bk[jp][1], bk[jp][2], bk[jp][3], sKl + swz(row, ch));
            }
            #pragma unroll
            for (int jp = 0; jp < 4; jp++) {
                MMAF(S[2*jp],   QAh[kk], bk[jp][0], bk[jp][1]);
                MMAF(S[2*jp+1], QAh[kk], bk[jp][2], bk[jp][3]);
            }
        }

        float mx0 = -1e30f, mx1 = -1e30f;
        #pragma unroll
        for (int g = 0; g < 8; g++) {
            S[g][0] *= 0.125f; S[g][1] *= 0.125f;
            S[g][2] *= 0.125f; S[g][3] *= 0.125f;
            mx0 = fmaxf(mx0, fmaxf(S[g][0], S[g][1]));
            mx1 = fmaxf(mx1, fmaxf(S[g][2], S[g][3]));
        }
        mx0 = fmaxf(mx0, __shfl_xor_sync(0xffffffffu, mx0, 1));
        mx0 = fmaxf(mx0, __shfl_xor_sync(0xffffffffu, mx0, 2));
        mx1 = fmaxf(mx1, __shfl_xor_sync(0xffffffffu, mx1, 1));
        mx1 = fmaxf(mx1, __shfl_xor_sync(0xffffffffu, mx1, 2));
        float mn0 = fmaxf(m0, mx0), mn1 = fmaxf(m1, mx1);
        float c0 = __expf(m0 - mn0), c1 = __expf(m1 - mn1);
        float sum0 = 0.f, sum1 = 0.f;
        #pragma unroll
        for (int g = 0; g < 8; g++) {
            S[g][0] = __expf(S[g][0] - mn0);
            S[g][1] = __expf(S[g][1] - mn0);
            S[g][2] = __expf(S[g][2] - mn1);
            S[g][3] = __expf(S[g][3] - mn1);
            sum0 += S[g][0] + S[g][1];
            sum1 += S[g][2] + S[g][3];
        }
        sum0 += __shfl_xor_sync(0xffffffffu, sum0, 1);
        sum0 += __shfl_xor_sync(0xffffffffu, sum0, 2);
        sum1 += __shfl_xor_sync(0xffffffffu, sum1, 1);
        sum1 += __shfl_xor_sync(0xffffffffu, sum1, 2);
        l0 = l0 * c0 + sum0;  l1 = l1 * c1 + sum1;
        m0 = mn0;  m1 = mn1;
        #pragma unroll
        for (int g = 0; g < 8; g++) {
            O[g][0] *= c0; O[g][1] *= c0;
            O[g][2] *= c1; O[g][3] *= c1;
        }

        #pragma unroll
        for (int kk = 0; kk < 4; kk++) {
            uint32_t pah[4], pal[4];
            {
                float* A0 = S[2*kk];
                float* A1 = S[2*kk+1];
                pah[0] = pack_bf2(A0[0], A0[1]);
                pah[1] = pack_bf2(A0[2], A0[3]);
                pah[2] = pack_bf2(A1[0], A1[1]);
                pah[3] = pack_bf2(A1[2], A1[3]);
                float2 f0 = unpack_bf2(pah[0]), f1 = unpack_bf2(pah[1]);
                float2 f2 = unpack_bf2(pah[2]), f3 = unpack_bf2(pah[3]);
                pal[0] = pack_bf2(A0[0] - f0.x, A0[1] - f0.y);
                pal[1] = pack_bf2(A0[2] - f1.x, A0[3] - f1.y);
                pal[2] = pack_bf2(A1[0] - f2.x, A1[1] - f2.y);
                pal[3] = pack_bf2(A1[2] - f3.x, A1[3] - f3.y);
            }
            uint32_t bv[4][4];
            #pragma unroll
            for (int jp = 0; jp < 4; jp++) {
                int row = kk * 16 + lr + ((sel & 1) ? 8 : 0);
                int ch  = 2 * jp + (sel >> 1);
                LDM4T(bv[jp][0], bv[jp][1], bv[jp][2], bv[jp][3], sVh + swz(row, ch));
            }
            #pragma unroll
            for (int jp = 0; jp < 4; jp++) {
                MMAF(O[2*jp],   pah, bv[jp][0], bv[jp][1]);
                MMAF(O[2*jp+1], pah, bv[jp][2], bv[jp][3]);
                MMAF(O[2*jp],   pal, bv[jp][0], bv[jp][1]);
                MMAF(O[2*jp+1], pal, bv[jp][2], bv[jp][3]);
            }
            #pragma unroll
            for (int jp = 0; jp < 4; jp++) {
                int row = kk * 16 + lr + ((sel & 1) ? 8 : 0);
                int ch  = 2 * jp + (sel >> 1);
                LDM4T(bv[jp][0], bv[jp][1], bv[jp][2], bv[jp][3], sVl + swz(row, ch));
            }
            #pragma unroll
            for (int jp = 0; jp < 4; jp++) {
                MMAF(O[2*jp],   pah, bv[jp][0], bv[jp][1]);
                MMAF(O[2*jp+1], pah, bv[jp][2], bv[jp][3]);
            }
        }

        __syncthreads();
        if (kt + 2 < 32) ISSUE_KV(kt + 2, sb + 32768 + (kt & 1) * 32768);
        if (kt + 1 < 32) {
            if (kt + 2 < 32) CPA_WAIT1(); else CPA_WAIT0();
            __syncthreads();
        }
    }
    #undef ISSUE_KV

    {
        float inv0 = 1.f / l0, inv1 = 1.f / l1;
        int row = b * SQL + qt * 128 + w * 16 + (lane >> 2);
        size_t base = (size_t)row * HID + h * HD + (lane & 3) * 2;
        #pragma unroll
        for (int g = 0; g < 8; g++) {
            float x0 = O[g][0] * inv0, x1 = O[g][1] * inv0;
            float y0 = O[g][2] * inv1, y1 = O[g][3] * inv1;
            __nv_bfloat16 h0 = __float2bfloat16(x0), h1 = __float2bfloat16(x1);
            __nv_bfloat16 g0 = __float2bfloat16(y0), g1 = __float2bfloat16(y1);
            *(__nv_bfloat162*)(xout + base + 8 * g) = __halves2bfloat162(h0, h1);
            *(__nv_bfloat162*)(xout + NQ + base + 8 * g) =
                __halves2bfloat162(__float2bfloat16(x0 - __bfloat162float(h0)),
                                   __float2bfloat16(x1 - __bfloat162float(h1)));
            *(__nv_bfloat162*)(xout + base + 8 * HID + 8 * g) = __halves2bfloat162(g0, g1);
            *(__nv_bfloat162*)(xout + NQ + base + 8 * HID + 8 * g) =
                __halves2bfloat162(__float2bfloat16(y0 - __bfloat162float(g0)),
                                   __float2bfloat16(y1 - __bfloat162float(g1)));
        }
    }
}

// ---------------------------------------------------------------------------
extern "C" void kernel_launch(void* const* d_in, const int* in_sizes, int n_in,
                              void* d_out, int out_size)
{
    const float* xq   = (const float*)d_in[0];
    const float* xkv  = (const float*)d_in[1];
    const float* Wq   = (const float*)d_in[2];
    const float* Wkv  = (const float*)d_in[3];
    const float* Wout = (const float*)d_in[4];
    const float* bout = (const float*)d_in[5];
    float* out = (float*)d_out;

    void *p_xq, *p_xkv, *p_wq, *p_wkv, *p_wo, *p_x, *p_qa, *p_kva;
    cudaGetSymbolAddress(&p_xq,  s_xq);
    cudaGetSymbolAddress(&p_xkv, s_xkv);
    cudaGetSymbolAddress(&p_wq,  s_wq);
    cudaGetSymbolAddress(&p_wkv, s_wkv);
    cudaGetSymbolAddress(&p_wo,  s_wo);
    cudaGetSymbolAddress(&p_x,   s_x);
    cudaGetSymbolAddress(&p_qa,  s_qa);
    cudaGetSymbolAddress(&p_kva, s_kva);

    cudaFuncSetAttribute(attn_mma,
        cudaFuncAttributeMaxDynamicSharedMemorySize, AT_SMEM);
    cudaFuncSetAttribute(gemm_mma4<1>,
        cudaFuncAttributeMaxDynamicSharedMemorySize, G4_SMEM);
    cudaFuncSetAttribute(gemm_mma4<2>,
        cudaFuncAttributeMaxDynamicSharedMemorySize, G4_SMEM);

    auto sp = [](const float* X, void* S, int n) {
        split_bf16_k<<<(n / 4 + 255) / 256, 256>>>(X, (__nv_bfloat16*)S, n);
    };
    sp(xq,   p_xq,  NB * SQL * HID);
    sp(xkv,  p_xkv, NB * SKV * HID);
    sp(Wq,   p_wq,  HID * HID);
    sp(Wkv,  p_wkv, 2 * HID * HID);
    sp(Wout, p_wo,  HID * HID);

    // q = xq @ Wq^T  -> split-bf16 directly into s_qa
    gemm_mma4<2><<<dim3(HID / 128, (NB * SQL) / 128), 128, G4_SMEM>>>(
        (const __nv_bfloat16*)p_xq, (const __nv_bfloat16*)p_wq,
        nullptr, p_qa, NB * SQL, HID);

    // kv = xkv @ Wkv^T  -> split-bf16 directly into s_kva
    gemm_mma4<2><<<dim3((2 * HID) / 128, (NB * SKV) / 128), 128, G4_SMEM>>>(
        (const __nv_bfloat16*)p_xkv, (const __nv_bfloat16*)p_wkv,
        nullptr, p_kva, NB * SKV, 2 * HID);

    // attention (writes split-bf16 x directly)
    attn_mma<<<dim3(SQL / 128, NB * NH), 256, AT_SMEM>>>(
        (const __nv_bfloat16*)p_qa, (const __nv_bfloat16*)p_kva,
        (__nv_bfloat16*)p_x);

    // out = x @ Wout^T + bout
    gemm_mma4<1><<<dim3(HID / 128, (NB * SQL) / 128), 128, G4_SMEM>>>(
        (const __nv_bfloat16*)p_x, (const __nv_bfloat16*)p_wo,
        bout, out, NB * SQL, HID);
}

// round 9
// speedup vs baseline: 3.7083x; 1.0249x over previous
#include <cuda_runtime.h>
#include <cuda_bf16.h>
#include <math.h>
#include <stdint.h>

#define HID 1024
#define NH  16
#define HD  64
#define NB  4
#define SQL 1024
#define SKV 2048

// ---------------- scratch (__device__ globals; no allocs allowed) ----------
__device__ __nv_bfloat16 s_xq [(size_t)2 * NB * SQL * HID];
__device__ __nv_bfloat16 s_xkv[(size_t)2 * NB * SKV * HID];
__device__ __nv_bfloat16 s_wq [(size_t)2 * HID * HID];
__device__ __nv_bfloat16 s_wkv[(size_t)2 * 2 * HID * HID];
__device__ __nv_bfloat16 s_wo [(size_t)2 * HID * HID];
__device__ __nv_bfloat16 s_x  [(size_t)2 * NB * SQL * HID];
__device__ __nv_bfloat16 s_qa [(size_t)2 * NB * SQL * HID];
__device__ __nv_bfloat16 s_kva[(size_t)2 * NB * SKV * 2 * HID];

// ---------------------------------------------------------------------------
static __device__ __forceinline__ uint32_t smem_u32(const void* p) {
    uint32_t a;
    asm("{ .reg .u64 t; cvta.to.shared.u64 t, %1; cvt.u32.u64 %0, t; }"
        : "=r"(a) : "l"(p));
    return a;
}

#define CPA16(dst, src) \
    asm volatile("cp.async.cg.shared.global [%0], [%1], 16;" \
                 :: "r"(dst), "l"(src) : "memory")
#define CPA_COMMIT() asm volatile("cp.async.commit_group;" ::: "memory")
#define CPA_WAIT2()  asm volatile("cp.async.wait_group 2;" ::: "memory")
#define CPA_WAIT1()  asm volatile("cp.async.wait_group 1;" ::: "memory")
#define CPA_WAIT0()  asm volatile("cp.async.wait_group 0;" ::: "memory")

#define LDM4(r0, r1, r2, r3, addr) \
    asm volatile("ldmatrix.sync.aligned.m8n8.x4.shared.b16 {%0,%1,%2,%3}, [%4];" \
                 : "=r"(r0), "=r"(r1), "=r"(r2), "=r"(r3) : "r"(addr))
#define LDM4T(r0, r1, r2, r3, addr) \
    asm volatile("ldmatrix.sync.aligned.m8n8.x4.trans.shared.b16 {%0,%1,%2,%3}, [%4];" \
                 : "=r"(r0), "=r"(r1), "=r"(r2), "=r"(r3) : "r"(addr))

#define MMAF(d, a, b0, b1) \
    asm volatile("mma.sync.aligned.m16n8k16.row.col.f32.bf16.bf16.f32 " \
                 "{%0,%1,%2,%3}, {%4,%5,%6,%7}, {%8,%9}, {%0,%1,%2,%3};" \
                 : "+f"((d)[0]), "+f"((d)[1]), "+f"((d)[2]), "+f"((d)[3]) \
                 : "r"((a)[0]), "r"((a)[1]), "r"((a)[2]), "r"((a)[3]), \
                   "r"(b0), "r"(b1))

static __device__ __forceinline__ uint32_t sw(int r, int c) {
    return (uint32_t)(r * 64 + ((c ^ ((r >> 1) & 3)) * 16));
}
static __device__ __forceinline__ uint32_t swz(int r, int c) {
    return (uint32_t)(r * 128 + ((c ^ (r & 7)) * 16));
}

static __device__ __forceinline__ uint32_t pack_bf2(float lo, float hi) {
    __nv_bfloat162 t = __float22bfloat162_rn(make_float2(lo, hi));
    return *(uint32_t*)&t;
}
static __device__ __forceinline__ float2 unpack_bf2(uint32_t u) {
    __nv_bfloat162 t = *(__nv_bfloat162*)&u;
    return __bfloat1622float2(t);
}

// ---------------------------------------------------------------------------
__global__ void split_bf16_k(const float* __restrict__ X,
                             __nv_bfloat16* __restrict__ S, int n)
{
    int i = (blockIdx.x * blockDim.x + threadIdx.x) * 4;
    if (i >= n) return;
    float4 x = *(const float4*)(X + i);
    float v[4] = {x.x, x.y, x.z, x.w};
    __nv_bfloat16 h[4], l[4];
    #pragma unroll
    for (int j = 0; j < 4; j++) {
        h[j] = __float2bfloat16(v[j]);
        l[j] = __float2bfloat16(v[j] - __bfloat162float(h[j]));
    }
    *(__nv_bfloat162*)(S + i)         = __halves2bfloat162(h[0], h[1]);
    *(__nv_bfloat162*)(S + i + 2)     = __halves2bfloat162(h[2], h[3]);
    *(__nv_bfloat162*)(S + n + i)     = __halves2bfloat162(l[0], l[1]);
    *(__nv_bfloat162*)(S + n + i + 2) = __halves2bfloat162(l[2], l[3]);
}

// ---------------------------------------------------------------------------
// Split-bf16 NT GEMM v5: 6-slot ring (3 A-pairs + 3 B-pairs), distance-2
// prefetch on both operands, ONE barrier per k-block.
// Block 128x128, 4 warps, warp tile 64x64, BK=32.
// Per k-block: d += Ah*Bh + Al*Bh + Ah*Bl.
// ---------------------------------------------------------------------------
#define G5_SLOT 16384
#define G5_SMEM (6 * G5_SLOT)           // 98304; 2 CTAs/SM (192KB <= 228KB)

template<int OMODE>
__global__ __launch_bounds__(128, 2) void gemm_mma5(
    const __nv_bfloat16* __restrict__ A, const __nv_bfloat16* __restrict__ B,
    const float* __restrict__ bias, void* __restrict__ Cv, int M, int N)
{
    extern __shared__ __align__(1024) char smem[];
    const uint32_t sb = smem_u32(smem);

    const int tid  = threadIdx.x;
    const int wid  = tid >> 5;
    const int lane = tid & 31;
    const int m0   = blockIdx.y * 128;
    const int n0   = blockIdx.x * 128;
    const int wm   = wid & 1;
    const int wn   = wid >> 1;

    const size_t MK = (size_t)M * HID, NK = (size_t)N * HID;
    const int NKB = 32;

    #define PRE_A(kb, s) do {                                                 \
        uint32_t _ba = sb + (s) * G5_SLOT;                                    \
        _Pragma("unroll")                                                     \
        for (int _q = 0; _q < 4; _q++) {                                      \
            int _ch = tid + _q * 128;                                         \
            int _r = _ch >> 2, _c = _ch & 3;                                  \
            const __nv_bfloat16* _p = A + (size_t)(m0 + _r) * HID + (kb) * 32 + _c * 8; \
            CPA16(_ba + sw(_r, _c), _p);                                      \
            CPA16(_ba + 8192 + sw(_r, _c), _p + MK);                          \
        }                                                                     \
        CPA_COMMIT();                                                         \
    } while (0)
    #define PRE_B(kb, s) do {                                                 \
        uint32_t _ba = sb + (3 + (s)) * G5_SLOT;                              \
        _Pragma("unroll")                                                     \
        for (int _q = 0; _q < 4; _q++) {                                      \
            int _ch = tid + _q * 128;                                         \
            int _r = _ch >> 2, _c = _ch & 3;                                  \
            const __nv_bfloat16* _p = B + (size_t)(n0 + _r) * HID + (kb) * 32 + _c * 8; \
            CPA16(_ba + sw(_r, _c), _p);                                      \
            CPA16(_ba + 8192 + sw(_r, _c), _p + NK);                          \
        }                                                                     \
        CPA_COMMIT();                                                         \
    } while (0)

    float d[4][8][4] = {};

    PRE_A(0, 0); PRE_B(0, 0); PRE_A(1, 1); PRE_B(1, 1);

    #pragma unroll 1
    for (int kb = 0; kb < NKB; kb++) {
        if (kb < NKB - 1) CPA_WAIT2(); else CPA_WAIT0();
        __syncthreads();        // the ONLY barrier per iteration

        const int slot = kb % 3;
        const uint32_t ah_base = sb + slot * G5_SLOT;
        const uint32_t al_base = ah_base + 8192;
        const uint32_t bh_base = sb + (3 + slot) * G5_SLOT;
        const uint32_t bl_base = bh_base + 8192;

        #pragma unroll
        for (int ks = 0; ks < 2; ks++) {
            const int ar = wm * 64 + (lane & 15);
            const int ac = ks * 2 + ((lane >> 4) & 1);
            const int br = wn * 64 + ((lane >> 4) & 1) * 8 + (lane & 7);
            const int bc = ks * 2 + ((lane >> 3) & 1);

            uint32_t ah[4][4], bh[8][2];
            #pragma unroll
            for (int mi = 0; mi < 4; mi++)
                LDM4(ah[mi][0], ah[mi][1], ah[mi][2], ah[mi][3],
                     ah_base + sw(ar + mi * 16, ac));
            #pragma unroll
            for (int ni = 0; ni < 4; ni++) {
                uint32_t r0, r1, r2, r3;
                LDM4(r0, r1, r2, r3, bh_base + sw(br + ni * 16, bc));
                bh[ni * 2][0] = r0;     bh[ni * 2][1] = r1;
                bh[ni * 2 + 1][0] = r2; bh[ni * 2 + 1][1] = r3;
            }
            #pragma unroll
            for (int mi = 0; mi < 4; mi++)
                #pragma unroll
                for (int nj = 0; nj < 8; nj++)
                    MMAF(d[mi][nj], ah[mi], bh[nj][0], bh[nj][1]);

            {   // Al * Bh
                uint32_t al[4][4];
                #pragma unroll
                for (int mi = 0; mi < 4; mi++)
                    LDM4(al[mi][0], al[mi][1], al[mi][2], al[mi][3],
                         al_base + sw(ar + mi * 16, ac));
                #pragma unroll
                for (int mi = 0; mi < 4; mi++)
                    #pragma unroll
                    for (int nj = 0; nj < 8; nj++)
                        MMAF(d[mi][nj], al[mi], bh[nj][0], bh[nj][1]);
            }
            {   // Ah * Bl
                uint32_t bl[8][2];
                #pragma unroll
                for (int ni = 0; ni < 4; ni++) {
                    uint32_t r0, r1, r2, r3;
                    LDM4(r0, r1, r2, r3, bl_base + sw(br + ni * 16, bc));
                    bl[ni * 2][0] = r0;     bl[ni * 2][1] = r1;
                    bl[ni * 2 + 1][0] = r2; bl[ni * 2 + 1][1] = r3;
                }
                #pragma unroll
                for (int mi = 0; mi < 4; mi++)
                    #pragma unroll
                    for (int nj = 0; nj < 8; nj++)
                        MMAF(d[mi][nj], ah[mi], bl[nj][0], bl[nj][1]);
            }
        }

        // prefetch kb+2 into slot (kb+2)%3 == slot of kb-1 (drained before
        // this iteration's top barrier) — no post-compute barrier needed.
        if (kb + 2 < NKB) {
            PRE_A(kb + 2, (kb + 2) % 3);
            PRE_B(kb + 2, (kb + 2) % 3);
        }
    }
    #undef PRE_A
    #undef PRE_B

    const int row0 = m0 + wm * 64 + (lane >> 2);
    const int col0 = n0 + wn * 64 + (lane & 3) * 2;

    if (OMODE == 1) {
        float* C = (float*)Cv;
        #pragma unroll
        for (int mi = 0; mi < 4; mi++) {
            #pragma unroll
            for (int nj = 0; nj < 8; nj++) {
                int r = row0 + mi * 16;
                int cc = col0 + nj * 8;
                float b0 = __ldg(bias + cc), b1 = __ldg(bias + cc + 1);
                *(float2*)(C + (size_t)r * N + cc) =
                    make_float2(d[mi][nj][0] + b0, d[mi][nj][1] + b1);
                *(float2*)(C + (size_t)(r + 8) * N + cc) =
                    make_float2(d[mi][nj][2] + b0, d[mi][nj][3] + b1);
            }
        }
    } else {
        __nv_bfloat16* C = (__nv_bfloat16*)Cv;
        const size_t MN = (size_t)M * N;
        #pragma unroll
        for (int mi = 0; mi < 4; mi++) {
            #pragma unroll
            for (int nj = 0; nj < 8; nj++) {
                int r = row0 + mi * 16;
                int cc = col0 + nj * 8;
                #pragma unroll
                for (int half = 0; half < 2; half++) {
                    float v0 = d[mi][nj][half * 2];
                    float v1 = d[mi][nj][half * 2 + 1];
                    size_t off = (size_t)(r + half * 8) * N + cc;
                    __nv_bfloat16 h0 = __float2bfloat16(v0);
                    __nv_bfloat16 h1 = __float2bfloat16(v1);
                    *(__nv_bfloat162*)(C + off) = __halves2bfloat162(h0, h1);
                    *(__nv_bfloat162*)(C + MN + off) = __halves2bfloat162(
                        __float2bfloat16(v0 - __bfloat162float(h0)),
                        __float2bfloat16(v1 - __bfloat162float(h1)));
                }
            }
        }
    }
}

// ---------------------------------------------------------------------------
// Split-bf16 mma.sync flash attention, 3-stage KV ring, one barrier per tile.
// ---------------------------------------------------------------------------
#define AT_SMEM (32768 + 3 * 32768)     // 131072

__global__ __launch_bounds__(256, 1) void attn_mma(
    const __nv_bfloat16* __restrict__ q,
    const __nv_bfloat16* __restrict__ kvs,
    __nv_bfloat16* __restrict__ xout)
{
    extern __shared__ __align__(1024) char smem[];
    const uint32_t sb  = smem_u32(smem);
    const uint32_t sQh = sb, sQl = sb + 16384;

    const int tid  = threadIdx.x;
    const int lane = tid & 31;
    const int w    = tid >> 5;
    const int lr   = lane & 7;
    const int sel  = lane >> 3;

    const int qt = blockIdx.x;
    const int bh = blockIdx.y;
    const int b  = bh >> 4;
    const int h  = bh & 15;

    const size_t NQ  = (size_t)NB * SQL * HID;
    const size_t NKV = (size_t)NB * SKV * 2 * HID;

    const __nv_bfloat16* Qb = q   + (size_t)(b * SQL + qt * 128) * HID + h * HD;
    const __nv_bfloat16* Kb = kvs + (size_t)b * SKV * 2 * HID + h * HD;

    {
        #pragma unroll
        for (int qq = 0; qq < 4; qq++) {
            int ch = tid * 4 + qq;
            int r = ch >> 3, c = ch & 7;
            const __nv_bfloat16* src = Qb + (size_t)r * HID + c * 8;
            CPA16(sQh + swz(r, c), src);
            CPA16(sQl + swz(r, c), src + NQ);
        }
    }
    #define ISSUE_KV(t) do {                                                  \
        int _kv0 = (t) * 64;                                                  \
        uint32_t _st = sb + 32768 + ((t) % 3) * 32768;                        \
        _Pragma("unroll")                                                     \
        for (int _qq = 0; _qq < 2; _qq++) {                                   \
            int _ch = tid * 2 + _qq;                                          \
            int _r = _ch >> 3, _c = _ch & 7;                                  \
            const __nv_bfloat16* _k = Kb + (size_t)(_kv0 + _r) * 2048 + _c * 8; \
            uint32_t _d = swz(_r, _c);                                        \
            CPA16(_st +         _d, _k);                                      \
            CPA16(_st + 8192  + _d, _k + NKV);                                \
            CPA16(_st + 16384 + _d, _k + HID);                                \
            CPA16(_st + 24576 + _d, _k + HID + NKV);                          \
        }                                                                     \
        CPA_COMMIT();                                                         \
    } while (0)

    CPA_COMMIT();           // Q group
    ISSUE_KV(0);
    ISSUE_KV(1);
    CPA_WAIT1();            // Q + KV0 complete
    __syncthreads();

    uint32_t QAh[4][4], QAl[4][4];
    {
        const int r0 = w * 16;
        #pragma unroll
        for (int kk = 0; kk < 4; kk++) {
            int row = r0 + lr + ((sel & 1) ? 8 : 0);
            int ch  = 2 * kk + (sel >> 1);
            LDM4(QAh[kk][0], QAh[kk][1], QAh[kk][2], QAh[kk][3], sQh + swz(row, ch));
            LDM4(QAl[kk][0], QAl[kk][1], QAl[kk][2], QAl[kk][3], sQl + swz(row, ch));
        }
    }

    float O[8][4] = {};
    float m0 = -1e30f, m1 = -1e30f, l0 = 0.f, l1 = 0.f;

    #pragma unroll 1
    for (int kt = 0; kt < 32; kt++) {
        const uint32_t st  = sb + 32768 + (kt % 3) * 32768;
        const uint32_t sKh = st, sKl = st + 8192;
        const uint32_t sVh = st + 16384, sVl = st + 24576;

        float S[8][4];
        #pragma unroll
        for (int g = 0; g < 8; g++)
            S[g][0] = S[g][1] = S[g][2] = S[g][3] = 0.f;

        #pragma unroll
        for (int kk = 0; kk < 4; kk++) {
            uint32_t bk[4][4];
            #pragma unroll
            for (int jp = 0; jp < 4; jp++) {
                int row = jp * 16 + lr + ((sel & 2) ? 8 : 0);
                int ch  = 2 * kk + (sel & 1);
                LDM4(bk[jp][0], bk[jp][1], bk[jp][2], bk[jp][3], sKh + swz(row, ch));
            }
            #pragma unroll
            for (int jp = 0; jp < 4; jp++) {
                MMAF(S[2*jp],   QAh[kk], bk[jp][0], bk[jp][1]);
                MMAF(S[2*jp+1], QAh[kk], bk[jp][2], bk[jp][3]);
                MMAF(S[2*jp],   QAl[kk], bk[jp][0], bk[jp][1]);
                MMAF(S[2*jp+1], QAl[kk], bk[jp][2], bk[jp][3]);
            }
        }
        #pragma unroll
        for (int kk = 0; kk < 4; kk++) {
            uint32_t bk[4][4];
            #pragma unroll
            for (int jp = 0; jp < 4; jp++) {
                int row = jp * 16 + lr + ((sel & 2) ? 8 : 0);
                int ch  = 2 * kk + (sel & 1);
                LDM4(bk[jp][0], bk[jp][1], bk[jp][2], bk[jp][3], sKl + swz(row, ch));
            }
            #pragma unroll
            for (int jp = 0; jp < 4; jp++) {
                MMAF(S[2*jp],   QAh[kk], bk[jp][0], bk[jp][1]);
                MMAF(S[2*jp+1], QAh[kk], bk[jp][2], bk[jp][3]);
            }
        }

        float mx0 = -1e30f, mx1 = -1e30f;
        #pragma unroll
        for (int g = 0; g < 8; g++) {
            S[g][0] *= 0.125f; S[g][1] *= 0.125f;
            S[g][2] *= 0.125f; S[g][3] *= 0.125f;
            mx0 = fmaxf(mx0, fmaxf(S[g][0], S[g][1]));
            mx1 = fmaxf(mx1, fmaxf(S[g][2], S[g][3]));
        }
        mx0 = fmaxf(mx0, __shfl_xor_sync(0xffffffffu, mx0, 1));
        mx0 = fmaxf(mx0, __shfl_xor_sync(0xffffffffu, mx0, 2));
        mx1 = fmaxf(mx1, __shfl_xor_sync(0xffffffffu, mx1, 1));
        mx1 = fmaxf(mx1, __shfl_xor_sync(0xffffffffu, mx1, 2));
        float mn0 = fmaxf(m0, mx0), mn1 = fmaxf(m1, mx1);
        float c0 = __expf(m0 - mn0), c1 = __expf(m1 - mn1);
        float sum0 = 0.f, sum1 = 0.f;
        #pragma unroll
        for (int g = 0; g < 8; g++) {
            S[g][0] = __expf(S[g][0] - mn0);
            S[g][1] = __expf(S[g][1] - mn0);
            S[g][2] = __expf(S[g][2] - mn1);
            S[g][3] = __expf(S[g][3] - mn1);
            sum0 += S[g][0] + S[g][1];
            sum1 += S[g][2] + S[g][3];
        }
        sum0 += __shfl_xor_sync(0xffffffffu, sum0, 1);
        sum0 += __shfl_xor_sync(0xffffffffu, sum0, 2);
        sum1 += __shfl_xor_sync(0xffffffffu, sum1, 1);
        sum1 += __shfl_xor_sync(0xffffffffu, sum1, 2);
        l0 = l0 * c0 + sum0;  l1 = l1 * c1 + sum1;
        m0 = mn0;  m1 = mn1;
        #pragma unroll
        for (int g = 0; g < 8; g++) {
            O[g][0] *= c0; O[g][1] *= c0;
            O[g][2] *= c1; O[g][3] *= c1;
        }

        #pragma unroll
        for (int kk = 0; kk < 4; kk++) {
            uint32_t pah[4], pal[4];
            {
                float* A0 = S[2*kk];
                float* A1 = S[2*kk+1];
                pah[0] = pack_bf2(A0[0], A0[1]);
                pah[1] = pack_bf2(A0[2], A0[3]);
                pah[2] = pack_bf2(A1[0], A1[1]);
                pah[3] = pack_bf2(A1[2], A1[3]);
                float2 f0 = unpack_bf2(pah[0]), f1 = unpack_bf2(pah[1]);
                float2 f2 = unpack_bf2(pah[2]), f3 = unpack_bf2(pah[3]);
                pal[0] = pack_bf2(A0[0] - f0.x, A0[1] - f0.y);
                pal[1] = pack_bf2(A0[2] - f1.x, A0[3] - f1.y);
                pal[2] = pack_bf2(A1[0] - f2.x, A1[1] - f2.y);
                pal[3] = pack_bf2(A1[2] - f3.x, A1[3] - f3.y);
            }
            uint32_t bv[4][4];
            #pragma unroll
            for (int jp = 0; jp < 4; jp++) {
                int row = kk * 16 + lr + ((sel & 1) ? 8 : 0);
                int ch  = 2 * jp + (sel >> 1);
                LDM4T(bv[jp][0], bv[jp][1], bv[jp][2], bv[jp][3], sVh + swz(row, ch));
            }
            #pragma unroll
            for (int jp = 0; jp < 4; jp++) {
                MMAF(O[2*jp],   pah, bv[jp][0], bv[jp][1]);
                MMAF(O[2*jp+1], pah, bv[jp][2], bv[jp][3]);
                MMAF(O[2*jp],   pal, bv[jp][0], bv[jp][1]);
                MMAF(O[2*jp+1], pal, bv[jp][2], bv[jp][3]);
            }
            #pragma unroll
            for (int jp = 0; jp < 4; jp++) {
                int row = kk * 16 + lr + ((sel & 1) ? 8 : 0);
                int ch  = 2 * jp + (sel >> 1);
                LDM4T(bv[jp][0], bv[jp][1], bv[jp][2], bv[jp][3], sVl + swz(row, ch));
            }
            #pragma unroll
            for (int jp = 0; jp < 4; jp++) {
                MMAF(O[2*jp],   pah, bv[jp][0], bv[jp][1]);
                MMAF(O[2*jp+1], pah, bv[jp][2], bv[jp][3]);
            }
        }

        // prefetch kt+2 into stage (kt+2)%3 == stage of kt-1 (drained) —
        // no second barrier needed.
        if (kt + 2 < 32) ISSUE_KV(kt + 2);
        if (kt + 1 < 32) {
            if (kt + 2 < 32) CPA_WAIT1(); else CPA_WAIT0();
            __syncthreads();
        }
    }
    #undef ISSUE_KV

    {
        float inv0 = 1.f / l0, inv1 = 1.f / l1;
        int row = b * SQL + qt * 128 + w * 16 + (lane >> 2);
        size_t base = (size_t)row * HID + h * HD + (lane & 3) * 2;
        #pragma unroll
        for (int g = 0; g < 8; g++) {
            float x0 = O[g][0] * inv0, x1 = O[g][1] * inv0;
            float y0 = O[g][2] * inv1, y1 = O[g][3] * inv1;
            __nv_bfloat16 h0 = __float2bfloat16(x0), h1 = __float2bfloat16(x1);
            __nv_bfloat16 g0 = __float2bfloat16(y0), g1 = __float2bfloat16(y1);
            *(__nv_bfloat162*)(xout + base + 8 * g) = __halves2bfloat162(h0, h1);
            *(__nv_bfloat162*)(xout + NQ + base + 8 * g) =
                __halves2bfloat162(__float2bfloat16(x0 - __bfloat162float(h0)),
                                   __float2bfloat16(x1 - __bfloat162float(h1)));
            *(__nv_bfloat162*)(xout + base + 8 * HID + 8 * g) = __halves2bfloat162(g0, g1);
            *(__nv_bfloat162*)(xout + NQ + base + 8 * HID + 8 * g) =
                __halves2bfloat162(__float2bfloat16(y0 - __bfloat162float(g0)),
                                   __float2bfloat16(y1 - __bfloat162float(g1)));
        }
    }
}

// ---------------------------------------------------------------------------
extern "C" void kernel_launch(void* const* d_in, const int* in_sizes, int n_in,
                              void* d_out, int out_size)
{
    const float* xq   = (const float*)d_in[0];
    const float* xkv  = (const float*)d_in[1];
    const float* Wq   = (const float*)d_in[2];
    const float* Wkv  = (const float*)d_in[3];
    const float* Wout = (const float*)d_in[4];
    const float* bout = (const float*)d_in[5];
    float* out = (float*)d_out;

    void *p_xq, *p_xkv, *p_wq, *p_wkv, *p_wo, *p_x, *p_qa, *p_kva;
    cudaGetSymbolAddress(&p_xq,  s_xq);
    cudaGetSymbolAddress(&p_xkv, s_xkv);
    cudaGetSymbolAddress(&p_wq,  s_wq);
    cudaGetSymbolAddress(&p_wkv, s_wkv);
    cudaGetSymbolAddress(&p_wo,  s_wo);
    cudaGetSymbolAddress(&p_x,   s_x);
    cudaGetSymbolAddress(&p_qa,  s_qa);
    cudaGetSymbolAddress(&p_kva, s_kva);

    cudaFuncSetAttribute(attn_mma,
        cudaFuncAttributeMaxDynamicSharedMemorySize, AT_SMEM);
    cudaFuncSetAttribute(gemm_mma5<1>,
        cudaFuncAttributeMaxDynamicSharedMemorySize, G5_SMEM);
    cudaFuncSetAttribute(gemm_mma5<2>,
        cudaFuncAttributeMaxDynamicSharedMemorySize, G5_SMEM);

    auto sp = [](const float* X, void* S, int n) {
        split_bf16_k<<<(n / 4 + 255) / 256, 256>>>(X, (__nv_bfloat16*)S, n);
    };
    sp(xq,   p_xq,  NB * SQL * HID);
    sp(xkv,  p_xkv, NB * SKV * HID);
    sp(Wq,   p_wq,  HID * HID);
    sp(Wkv,  p_wkv, 2 * HID * HID);
    sp(Wout, p_wo,  HID * HID);

    // q = xq @ Wq^T  -> split-bf16 directly into s_qa
    gemm_mma5<2><<<dim3(HID / 128, (NB * SQL) / 128), 128, G5_SMEM>>>(
        (const __nv_bfloat16*)p_xq, (const __nv_bfloat16*)p_wq,
        nullptr, p_qa, NB * SQL, HID);

    // kv = xkv @ Wkv^T  -> split-bf16 directly into s_kva
    gemm_mma5<2><<<dim3((2 * HID) / 128, (NB * SKV) / 128), 128, G5_SMEM>>>(
        (const __nv_bfloat16*)p_xkv, (const __nv_bfloat16*)p_wkv,
        nullptr, p_kva, NB * SKV, 2 * HID);

    // attention (writes split-bf16 x directly)
    attn_mma<<<dim3(SQL / 128, NB * NH), 256, AT_SMEM>>>(
        (const __nv_bfloat16*)p_qa, (const __nv_bfloat16*)p_kva,
        (__nv_bfloat16*)p_x);

    // out = x @ Wout^T + bout
    gemm_mma5<1><<<dim3(HID / 128, (NB * SQL) / 128), 128, G5_SMEM>>>(
        (const __nv_bfloat16*)p_x, (const __nv_bfloat16*)p_wo,
        bout, out, NB * SQL, HID);
}